// round 11
// baseline (speedup 1.0000x reference)
#include <cuda_runtime.h>

#define NE 2049   // E is NE x NE
#define NH 2048   // Hx cols / Hy rows
#define NW 2047   // Hx rows / Hy cols
#define CFLf 0.35f

#define KF0 (-11.0f/6.0f)
#define KF1 (3.0f)
#define KF2 (-1.5f)
#define KF3 (1.0f/3.0f)
#define KB0 (-1.0f/3.0f)
#define KB1 (1.5f)
#define KB2 (-3.0f)
#define KB3 (11.0f/6.0f)

#define IT 8
#define A_INT_Y 254   // amper interior: i0 = 5 + 8*y, i in [5,2036]
#define A_BND_Y 27    // 17 row strips + 10 col strips
#define F_INT_Y 255   // faraday interior: i0 = 2 + 8*y, i in [2,2041]
#define F_BND_Y 13    // 8 row strips + 5 col strips

__device__ __forceinline__ void pf_l1(const void* p) {
    asm volatile("prefetch.global.L1 [%0];" :: "l"(p));
}

__device__ __forceinline__ void load_M(float beta, float delta, float gamma,
                                       float& a0, float& a1,
                                       float& m01, float& m11, float& m21) {
    a0  = -0.25f * beta + 0.1f * gamma;
    a1  =  0.25f * beta - 0.1f * gamma;
    m01 =  0.25f * beta + delta - 0.5f - 0.1f * gamma;
    m11 = -2.0f * delta;
    m21 = -0.25f * beta + delta + 0.5f + 0.1f * gamma;
}

// ===========================================================================
// Scalar point functions (verified) — boundary strips.
// ===========================================================================
__device__ void amper_point(int i, int j,
                            const float* __restrict__ Eb,
                            const float* __restrict__ Hxb,
                            const float* __restrict__ Hyb,
                            float a0, float a1, float m01, float m11, float m21,
                            float* __restrict__ Eob) {
    const bool ic = (i >= 2 && i <= NE - 3);
    const bool jc = (j >= 2 && j <= NE - 3);
    float s1 = 0.0f, s2 = 0.0f;

    if (ic && jc) {
        const float* r0 = Hyb + (size_t)(i - 2) * NW + (j - 2);
        const float* r1 = r0 + NW;
        const float* r2 = r1 + NW;
        const float* r3 = r2 + NW;
        s1 += a0  * r0[0] + a1  * r0[2]
            + m01 * r1[0] + m11 * r1[1] + m21 * r1[2]
            + a1  * r2[0] + a0  * r2[2]
            + a0  * r3[0] + a1  * r3[2];
        const float* x0 = Hxb + (size_t)(i - 2) * NH + (j - 2);
        const float* x1 = x0 + NH;
        const float* x2 = x1 + NH;
        s2 += a0 * x0[0] + m01 * x0[1] + a1 * x0[2] + a0 * x0[3]
            + m11 * x1[1]
            + a1 * x2[0] + m21 * x2[1] + a0 * x2[2] + a1 * x2[3];
    }
    if (i >= 1 && j <= NE - 6) {
        const float* r = Hyb + (size_t)(i - 1) * NW + j;
        s1 += KF0 * r[0] + KF1 * r[1] + KF2 * r[2] + KF3 * r[3];
    }
    if (i <= NE - 2 && j >= 5) {
        const float* r = Hyb + (size_t)i * NW + (j - 5);
        s1 += KB0 * r[0] + KB1 * r[1] + KB2 * r[2] + KB3 * r[3];
    }
    if (ic && (j == 1 || j == 2)) {
        const float* r = Hyb + (size_t)(i - 1) * NW + (j - 1);
        s1 += -r[0] + 3.0f * r[1] - 3.0f * r[2] + r[3];
    }
    if (ic && (j == NE - 3 || j == NE - 2)) {
        const float* r = Hyb + (size_t)i * NW + (j - 4);
        s1 += r[0] - 3.0f * r[1] + 3.0f * r[2] - r[3];
    }
    if (i <= NE - 6 && j >= 1) {
        const float* x = Hxb + (size_t)i * NH + (j - 1);
        s2 += KF0 * x[0] + KF1 * x[NH] + KF2 * x[2 * NH] + KF3 * x[3 * NH];
    }
    if (i >= 5 && j <= NE - 2) {
        const float* x = Hxb + (size_t)(i - 5) * NH + j;
        s2 += KB0 * x[0] + KB1 * x[NH] + KB2 * x[2 * NH] + KB3 * x[3 * NH];
    }
    if ((i == 1 || i == 2) && jc) {
        const float* x = Hxb + (size_t)(i - 1) * NH + (j - 1);
        s2 += -x[0] + 3.0f * x[NH] - 3.0f * x[2 * NH] + x[3 * NH];
    }
    if ((i == NE - 3 || i == NE - 2) && jc) {
        const float* x = Hxb + (size_t)(i - 4) * NH + j;
        s2 += x[0] - 3.0f * x[NH] + 3.0f * x[2 * NH] - x[3 * NH];
    }
    Eob[(size_t)i * NE + j] = Eb[(size_t)i * NE + j] + CFLf * (s1 - s2);
}

__device__ void faraday_point(int i, int j,
                              const float* __restrict__ Eb,
                              const float* __restrict__ Hxb,
                              const float* __restrict__ Hyb,
                              float a0, float a1, float m01, float m11, float m21,
                              float* __restrict__ Hxob,
                              float* __restrict__ Hyob) {
    if (i < NW && j < NH) {
        float s3 = 0.0f;
        if (j >= 1 && j <= NH - 2) {
            const float* e0 = Eb + (size_t)i * NE + (j - 1);
            const float* e1 = e0 + NE;
            const float* e2 = e1 + NE;
            s3 += a0 * e0[0] + m01 * e0[1] + a1 * e0[2] + a0 * e0[3]
                + m11 * e1[1]
                + a1 * e2[0] + m21 * e2[1] + a0 * e2[2] + a1 * e2[3];
        }
        if (i <= NH - 4) {
            const float* e = Eb + (size_t)(i + 1) * NE + j;
            s3 += -1.5f * e[0] + 2.0f * e[NE] - 0.5f * e[2 * NE];
        }
        if (i >= 2) {
            const float* e = Eb + (size_t)(i - 1) * NE + (j + 1);
            s3 += 0.5f * e[0] - 2.0f * e[NE] + 1.5f * e[2 * NE];
        }
        const size_t off = (size_t)i * NH + j;
        Hxob[off] = Hxb[off] - CFLf * s3;
    }
    if (i < NH && j < NW) {
        float s4 = 0.0f;
        if (i >= 1 && i <= NH - 2) {
            const float* e0 = Eb + (size_t)(i - 1) * NE + j;
            const float* e1 = e0 + NE;
            const float* e2 = e1 + NE;
            const float* e3 = e2 + NE;
            s4 += a0  * e0[0] + a1  * e0[2]
                + m01 * e1[0] + m11 * e1[1] + m21 * e1[2]
                + a1  * e2[0] + a0  * e2[2]
                + a0  * e3[0] + a1  * e3[2];
        }
        if (j <= NH - 4) {
            const float* e = Eb + (size_t)i * NE + (j + 1);
            s4 += -1.5f * e[0] + 2.0f * e[1] - 0.5f * e[2];
        }
        if (j >= 2) {
            const float* e = Eb + (size_t)(i + 1) * NE + (j - 1);
            s4 += 0.5f * e[0] - 2.0f * e[1] + 1.5f * e[2];
        }
        const size_t off = (size_t)i * NW + j;
        Hyob[off] = Hyb[off] + CFLf * s4;
    }
}

// ===========================================================================
// Fused amper: interior (IT=8) + boundary strips. R5 structure + L1 prefetch.
// ===========================================================================
__global__ __launch_bounds__(256)
void amper_kernel(const float* __restrict__ E,
                  const float* __restrict__ Hx,
                  const float* __restrict__ Hy,
                  const float* __restrict__ pb,
                  const float* __restrict__ pd,
                  const float* __restrict__ pg,
                  float* __restrict__ Eo) {
    const int b = blockIdx.z;
    float a0, a1, m01, m11, m21;
    load_M(*pb, *pd, *pg, a0, a1, m01, m11, m21);

    const float* Eb  = E  + (size_t)b * NE * NE;
    const float* Hxb = Hx + (size_t)b * NW * NH;
    const float* Hyb = Hy + (size_t)b * NH * NW;
    float* Eob = Eo + (size_t)b * NE * NE;

    if (blockIdx.y >= A_INT_Y) {
        const int y = blockIdx.y - A_INT_Y;
        if (y < 17) {
            const int i = (y < 5) ? y : 2037 + (y - 5);
            const int j = blockIdx.x * 256 + threadIdx.x;
            if (j >= NE) return;
            amper_point(i, j, Eb, Hxb, Hyb, a0, a1, m01, m11, m21, Eob);
        } else {
            const int c = y - 17;
            const int j = (c < 5) ? c : 2044 + (c - 5);
            const int i = 5 + blockIdx.x * 256 + threadIdx.x;
            if (i > 2036) return;
            amper_point(i, j, Eb, Hxb, Hyb, a0, a1, m01, m11, m21, Eob);
        }
        return;
    }

    // ---- interior: i0 = 5 + 8*y, j in [5, 2043] ----
    const int j = 5 + blockIdx.x * 256 + threadIdx.x;
    if (j > 2043) return;
    const int i0 = 5 + blockIdx.y * IT;

    const float a1k  = a1 + KB3;
    const float m21k = m21 + KF0;

    // Prefetch the E read-add lines (consumed only at the end).
    const size_t off = (size_t)i0 * NE + j;
#pragma unroll
    for (int k = 0; k < IT; k++) pf_l1(Eb + off + (size_t)k * NE);

    float acc[IT];
#pragma unroll
    for (int k = 0; k < IT; k++) acc[k] = 0.0f;

    // ---- s1: Hy rows i0-2 .. i0+8, window cols j-5 .. j+3 ----
    {
        const float* hy = Hyb + (size_t)(i0 - 2) * NW + (j - 5);
#pragma unroll
        for (int rr = 0; rr < IT + 3; ++rr) {
            // Prefetch next row's window (rows stay in-bounds: max i0+9 <= 2038 < 2048).
            pf_l1(hy + NW);
            pf_l1(hy + NW + 8);
            const bool uA = (rr <= IT - 1);
            const bool uB = (rr >= 1 && rr <= IT);
            const bool uC = (rr >= 2 && rr <= IT + 1);
            const bool uD = (rr >= 3);
            float c0 = 0.f, c1 = 0.f, c2 = 0.f, c4 = 0.f, c6 = 0.f, c7 = 0.f, c8 = 0.f;
            const float c3 = hy[3];
            const float c5 = hy[5];
            if (uC) { c0 = hy[0]; c1 = hy[1]; c2 = hy[2]; }
            if (uB) { c4 = hy[4]; c6 = hy[6]; c7 = hy[7]; c8 = hy[8]; }
            const float t = a0 * c3 + a1 * c5;
            if (uA) acc[rr]     += t;
            if (uB) acc[rr - 1] += m01 * c3 + m11 * c4 + m21k * c5
                                 + KF1 * c6 + KF2 * c7 + KF3 * c8;
            if (uC) acc[rr - 2] += KB0 * c0 + KB1 * c1 + KB2 * c2
                                 + a1k * c3 + a0 * c5;
            if (uD) acc[rr - 3] += t;
            hy += NW;
        }
    }

    // ---- s2 (subtract): Hx rows i0-5 .. i0+10, window cols j-2 .. j+1 ----
    {
        const float* hx = Hxb + (size_t)(i0 - 5) * NH + (j - 2);
#pragma unroll
        for (int rr = 0; rr < IT + 8; ++rr) {
            // Prefetch next row (max row i0+11 <= 2040 < 2047).
            pf_l1(hx + NH);
            pf_l1(hx + NH + 3);
            const bool vK0 = (rr <= IT - 1);
            const bool vK1 = (rr >= 1 && rr <= IT);
            const bool vK2 = (rr >= 2 && rr <= IT + 1);
            const bool vA  = (rr >= 3 && rr <= IT + 2);
            const bool vB  = (rr >= 4 && rr <= IT + 3);
            const bool vC  = (rr >= 5 && rr <= IT + 4);
            const bool vD  = (rr >= 6 && rr <= IT + 5);
            const bool vE  = (rr >= 7 && rr <= IT + 6);
            const bool vF  = (rr >= 8);
            float d0 = 0.f, d1 = 0.f, d2 = 0.f, d3 = 0.f;
            if (vA | vC) { d0 = hx[0]; d3 = hx[3]; }
            if (vA | vB | vC | vD | vE | vF) d1 = hx[1];
            if (vK0 | vK1 | vK2 | vA | vC) d2 = hx[2];
            if (vK0) acc[rr]     -= KB0 * d2;
            if (vK1) acc[rr - 1] -= KB1 * d2;
            if (vK2) acc[rr - 2] -= KB2 * d2;
            if (vA)  acc[rr - 3] -= a0 * d0 + m01 * d1 + a1k * d2 + a0 * d3;
            if (vB)  acc[rr - 4] -= m11 * d1;
            if (vC)  acc[rr - 5] -= a1 * d0 + m21k * d1 + a0 * d2 + a1 * d3;
            if (vD)  acc[rr - 6] -= KF1 * d1;
            if (vE)  acc[rr - 7] -= KF2 * d1;
            if (vF)  acc[rr - 8] -= KF3 * d1;
            hx += NH;
        }
    }

#pragma unroll
    for (int k = 0; k < IT; k++)
        Eob[off + (size_t)k * NE] = Eb[off + (size_t)k * NE] + CFLf * acc[k];
}

// ===========================================================================
// Fused faraday (Hx+Hy): interior (IT=8) + boundary strips. R5 + prefetch.
// ===========================================================================
__global__ __launch_bounds__(256)
void faraday_kernel(const float* __restrict__ E,
                    const float* __restrict__ Hx,
                    const float* __restrict__ Hy,
                    const float* __restrict__ pb,
                    const float* __restrict__ pd,
                    const float* __restrict__ pg,
                    float* __restrict__ Hxo,
                    float* __restrict__ Hyo) {
    const int b = blockIdx.z;
    float a0, a1, m01, m11, m21;
    load_M(*pb, *pd, *pg, a0, a1, m01, m11, m21);

    const float* Eb  = E  + (size_t)b * NE * NE;
    const float* Hxb = Hx + (size_t)b * NW * NH;
    const float* Hyb = Hy + (size_t)b * NH * NW;
    float* Hxob = Hxo + (size_t)b * NW * NH;
    float* Hyob = Hyo + (size_t)b * NH * NW;

    if (blockIdx.y >= F_INT_Y) {
        const int y = blockIdx.y - F_INT_Y;
        if (y < 8) {
            const int i = (y < 2) ? y : 2042 + (y - 2);
            const int j = blockIdx.x * 256 + threadIdx.x;
            if (j >= NH) return;
            faraday_point(i, j, Eb, Hxb, Hyb, a0, a1, m01, m11, m21, Hxob, Hyob);
        } else {
            const int c = y - 8;
            const int j = (c < 2) ? c : 2045 + (c - 2);
            const int i = 2 + blockIdx.x * 256 + threadIdx.x;
            if (i > 2041) return;
            faraday_point(i, j, Eb, Hxb, Hyb, a0, a1, m01, m11, m21, Hxob, Hyob);
        }
        return;
    }

    // ---- interior: i0 = 2 + 8*y, j in [2, 2044] ----
    const int j = 2 + blockIdx.x * 256 + threadIdx.x;
    if (j > 2044) return;
    const int i0 = 2 + blockIdx.y * IT;

    const float m11b = m11 - 1.5f;
    const float m21b = m21 + 2.0f;
    const float a1m2 = a1 - 2.0f;

    // Prefetch the Hx/Hy read-add lines (consumed only at the end).
    const size_t offx = (size_t)i0 * NH + j;
    const size_t offy = (size_t)i0 * NW + j;
#pragma unroll
    for (int k = 0; k < IT; k++) {
        pf_l1(Hxb + offx + (size_t)k * NH);
        pf_l1(Hyb + offy + (size_t)k * NW);
    }

    float sx[IT], sy[IT];
#pragma unroll
    for (int k = 0; k < IT; k++) { sx[k] = 0.0f; sy[k] = 0.0f; }

    const float* ep = Eb + (size_t)(i0 - 1) * NE + (j - 1);
#pragma unroll
    for (int rr = 0; rr < IT + 4; ++rr) {
        // Prefetch next E row's window (max row i0+11 <= 2045 <= 2048).
        pf_l1(ep + NE);
        pf_l1(ep + NE + 4);
        const bool w0 = (rr <= IT - 1);
        const bool w1 = (rr >= 1 && rr <= IT);
        const bool w2 = (rr >= 2 && rr <= IT + 1);
        const bool w3 = (rr >= 3 && rr <= IT + 2);
        const bool w4 = (rr >= 4);
        float e0 = 0.f, e2 = 0.f, e3 = 0.f, e4 = 0.f;
        const float e1 = ep[1];
        if (w1 | w2 | w3) e0 = ep[0];
        if (w0 | w1 | w2 | w3) { e2 = ep[2]; e3 = ep[3]; }
        if (w1) e4 = ep[4];

        const float ty = a0 * e1 + a1 * e3;
        if (w0) { sx[rr] += 0.5f * e2; sy[rr] += ty; }
        if (w1) {
            sx[rr - 1] += a0 * e0 + m01 * e1 + a1m2 * e2 + a0 * e3;
            sy[rr - 1] += m01 * e1 + m11b * e2 + m21b * e3 - 0.5f * e4;
        }
        if (w2) {
            sx[rr - 2] += m11b * e1 + 1.5f * e2;
            sy[rr - 2] += 0.5f * e0 + a1m2 * e1 + 1.5f * e2 + a0 * e3;
        }
        if (w3) {
            sx[rr - 3] += a1 * e0 + m21b * e1 + a0 * e2 + a1 * e3;
            sy[rr - 3] += ty;
        }
        if (w4) sx[rr - 4] -= 0.5f * e1;
        ep += NE;
    }

#pragma unroll
    for (int k = 0; k < IT; k++) {
        Hxob[offx + (size_t)k * NH] = Hxb[offx + (size_t)k * NH] - CFLf * sx[k];
        Hyob[offy + (size_t)k * NW] = Hyb[offy + (size_t)k * NW] + CFLf * sy[k];
    }
}

// ===========================================================================
extern "C" void kernel_launch(void* const* d_in, const int* in_sizes, int n_in,
                              void* d_out, int out_size) {
    const float* E0  = (const float*)d_in[0];
    const float* Hx0 = (const float*)d_in[1];
    const float* Hy0 = (const float*)d_in[2];
    const float* pb  = (const float*)d_in[3];
    const float* pd  = (const float*)d_in[4];
    const float* pg  = (const float*)d_in[5];

    const int B = in_sizes[0] / (NE * NE);

    const size_t nE  = (size_t)B * NE * NE;
    const size_t nHx = (size_t)B * NW * NH;
    const size_t nHy = (size_t)B * NH * NW;

    float* out = (float*)d_out;
    float* E2  = out;
    float* Hx2 = E2 + nE;
    float* Hy2 = Hx2 + nHx;
    float* E3  = Hy2 + nHy;
    float* Hx3 = E3 + nE;
    float* Hy3 = Hx3 + nHx;
    float* E4  = Hy3 + nHy;
    float* Hx4 = E4 + nE;
    float* Hy4 = Hx4 + nHx;

    dim3 blk(256);
    dim3 gA(9, A_INT_Y + A_BND_Y, B);  // x=9 for 2049-wide boundary rows
    dim3 gF(8, F_INT_Y + F_BND_Y, B);

    const float* Ein  = E0;
    const float* Hxin = Hx0;
    const float* Hyin = Hy0;
    float* Eouts[3]  = {E2, E3, E4};
    float* Hxouts[3] = {Hx2, Hx3, Hx4};
    float* Hyouts[3] = {Hy2, Hy3, Hy4};

    for (int s = 0; s < 3; s++) {
        amper_kernel<<<gA, blk>>>(Ein, Hxin, Hyin, pb, pd, pg, Eouts[s]);
        faraday_kernel<<<gF, blk>>>(Eouts[s], Hxin, Hyin, pb, pd, pg,
                                    Hxouts[s], Hyouts[s]);
        Ein = Eouts[s]; Hxin = Hxouts[s]; Hyin = Hyouts[s];
    }
}

// round 12
// speedup vs baseline: 1.0587x; 1.0587x over previous
#include <cuda_runtime.h>

#define NE 2049   // E is NE x NE
#define NH 2048   // Hx cols / Hy rows
#define NW 2047   // Hx rows / Hy cols
#define CFLf 0.35f

#define KF0 (-11.0f/6.0f)
#define KF1 (3.0f)
#define KF2 (-1.5f)
#define KF3 (1.0f/3.0f)
#define KB0 (-1.0f/3.0f)
#define KB1 (1.5f)
#define KB2 (-3.0f)
#define KB3 (11.0f/6.0f)

#define AIT 12        // amper rows per fused block (i0-1 .. i0+10)
#define FIT 8         // faraday rows per fused block (i0 .. i0+7)
#define FY  253       // fused interior i-tiles: i0 = 8 + 8*y, rows 8..2031
#define A_STRIP_Y 42  // 25 row strips + 17 col strips (amper remainder)

__device__ __forceinline__ void load_M(float beta, float delta, float gamma,
                                       float& a0, float& a1,
                                       float& m01, float& m11, float& m21) {
    a0  = -0.25f * beta + 0.1f * gamma;
    a1  =  0.25f * beta - 0.1f * gamma;
    m01 =  0.25f * beta + delta - 0.5f - 0.1f * gamma;
    m11 = -2.0f * delta;
    m21 = -0.25f * beta + delta + 0.5f + 0.1f * gamma;
}

// ===========================================================================
// Scalar point functions (verified) — remainder strips.
// ===========================================================================
__device__ void amper_point(int i, int j,
                            const float* __restrict__ Eb,
                            const float* __restrict__ Hxb,
                            const float* __restrict__ Hyb,
                            float a0, float a1, float m01, float m11, float m21,
                            float* __restrict__ Eob) {
    const bool ic = (i >= 2 && i <= NE - 3);
    const bool jc = (j >= 2 && j <= NE - 3);
    float s1 = 0.0f, s2 = 0.0f;

    if (ic && jc) {
        const float* r0 = Hyb + (size_t)(i - 2) * NW + (j - 2);
        const float* r1 = r0 + NW;
        const float* r2 = r1 + NW;
        const float* r3 = r2 + NW;
        s1 += a0  * r0[0] + a1  * r0[2]
            + m01 * r1[0] + m11 * r1[1] + m21 * r1[2]
            + a1  * r2[0] + a0  * r2[2]
            + a0  * r3[0] + a1  * r3[2];
        const float* x0 = Hxb + (size_t)(i - 2) * NH + (j - 2);
        const float* x1 = x0 + NH;
        const float* x2 = x1 + NH;
        s2 += a0 * x0[0] + m01 * x0[1] + a1 * x0[2] + a0 * x0[3]
            + m11 * x1[1]
            + a1 * x2[0] + m21 * x2[1] + a0 * x2[2] + a1 * x2[3];
    }
    if (i >= 1 && j <= NE - 6) {
        const float* r = Hyb + (size_t)(i - 1) * NW + j;
        s1 += KF0 * r[0] + KF1 * r[1] + KF2 * r[2] + KF3 * r[3];
    }
    if (i <= NE - 2 && j >= 5) {
        const float* r = Hyb + (size_t)i * NW + (j - 5);
        s1 += KB0 * r[0] + KB1 * r[1] + KB2 * r[2] + KB3 * r[3];
    }
    if (ic && (j == 1 || j == 2)) {
        const float* r = Hyb + (size_t)(i - 1) * NW + (j - 1);
        s1 += -r[0] + 3.0f * r[1] - 3.0f * r[2] + r[3];
    }
    if (ic && (j == NE - 3 || j == NE - 2)) {
        const float* r = Hyb + (size_t)i * NW + (j - 4);
        s1 += r[0] - 3.0f * r[1] + 3.0f * r[2] - r[3];
    }
    if (i <= NE - 6 && j >= 1) {
        const float* x = Hxb + (size_t)i * NH + (j - 1);
        s2 += KF0 * x[0] + KF1 * x[NH] + KF2 * x[2 * NH] + KF3 * x[3 * NH];
    }
    if (i >= 5 && j <= NE - 2) {
        const float* x = Hxb + (size_t)(i - 5) * NH + j;
        s2 += KB0 * x[0] + KB1 * x[NH] + KB2 * x[2 * NH] + KB3 * x[3 * NH];
    }
    if ((i == 1 || i == 2) && jc) {
        const float* x = Hxb + (size_t)(i - 1) * NH + (j - 1);
        s2 += -x[0] + 3.0f * x[NH] - 3.0f * x[2 * NH] + x[3 * NH];
    }
    if ((i == NE - 3 || i == NE - 2) && jc) {
        const float* x = Hxb + (size_t)(i - 4) * NH + j;
        s2 += x[0] - 3.0f * x[NH] + 3.0f * x[2 * NH] - x[3 * NH];
    }
    Eob[(size_t)i * NE + j] = Eb[(size_t)i * NE + j] + CFLf * (s1 - s2);
}

__device__ void faraday_point(int i, int j,
                              const float* __restrict__ Eb,
                              const float* __restrict__ Hxb,
                              const float* __restrict__ Hyb,
                              float a0, float a1, float m01, float m11, float m21,
                              float* __restrict__ Hxob,
                              float* __restrict__ Hyob) {
    if (i < NW && j < NH) {
        float s3 = 0.0f;
        if (j >= 1 && j <= NH - 2) {
            const float* e0 = Eb + (size_t)i * NE + (j - 1);
            const float* e1 = e0 + NE;
            const float* e2 = e1 + NE;
            s3 += a0 * e0[0] + m01 * e0[1] + a1 * e0[2] + a0 * e0[3]
                + m11 * e1[1]
                + a1 * e2[0] + m21 * e2[1] + a0 * e2[2] + a1 * e2[3];
        }
        if (i <= NH - 4) {
            const float* e = Eb + (size_t)(i + 1) * NE + j;
            s3 += -1.5f * e[0] + 2.0f * e[NE] - 0.5f * e[2 * NE];
        }
        if (i >= 2) {
            const float* e = Eb + (size_t)(i - 1) * NE + (j + 1);
            s3 += 0.5f * e[0] - 2.0f * e[NE] + 1.5f * e[2 * NE];
        }
        const size_t off = (size_t)i * NH + j;
        Hxob[off] = Hxb[off] - CFLf * s3;
    }
    if (i < NH && j < NW) {
        float s4 = 0.0f;
        if (i >= 1 && i <= NH - 2) {
            const float* e0 = Eb + (size_t)(i - 1) * NE + j;
            const float* e1 = e0 + NE;
            const float* e2 = e1 + NE;
            const float* e3 = e2 + NE;
            s4 += a0  * e0[0] + a1  * e0[2]
                + m01 * e1[0] + m11 * e1[1] + m21 * e1[2]
                + a1  * e2[0] + a0  * e2[2]
                + a0  * e3[0] + a1  * e3[2];
        }
        if (j <= NH - 4) {
            const float* e = Eb + (size_t)i * NE + (j + 1);
            s4 += -1.5f * e[0] + 2.0f * e[1] - 0.5f * e[2];
        }
        if (j >= 2) {
            const float* e = Eb + (size_t)(i + 1) * NE + (j - 1);
            s4 += 0.5f * e[0] - 2.0f * e[1] + 1.5f * e[2];
        }
        const size_t off = (size_t)i * NW + j;
        Hyob[off] = Hyb[off] + CFLf * s4;
    }
}

// ===========================================================================
// Fused step kernel: amper (tile + halo, all-interior) -> smem -> faraday.
// Interior slices: i0 = 8 + 8*y (y < FY), owned cols [jb, min(jb+255,2039)].
// Extra y-slices: amper remainder strips (rows 0-7 & 2032-2048 full width;
// cols 0-7 & 2040-2048 for rows 8-2031), via amper_point.
// ===========================================================================
__global__ __launch_bounds__(288)
void fused_step_kernel(const float* __restrict__ E,
                       const float* __restrict__ Hx,
                       const float* __restrict__ Hy,
                       const float* __restrict__ pb,
                       const float* __restrict__ pd,
                       const float* __restrict__ pg,
                       float* __restrict__ Eo,
                       float* __restrict__ Hxo,
                       float* __restrict__ Hyo) {
    const int b = blockIdx.z;
    const int tid = threadIdx.x;
    float a0, a1, m01, m11, m21;
    load_M(*pb, *pd, *pg, a0, a1, m01, m11, m21);

    const float* Eb  = E  + (size_t)b * NE * NE;
    const float* Hxb = Hx + (size_t)b * NW * NH;
    const float* Hyb = Hy + (size_t)b * NH * NW;
    float* Eob  = Eo  + (size_t)b * NE * NE;
    float* Hxob = Hxo + (size_t)b * NW * NH;
    float* Hyob = Hyo + (size_t)b * NH * NW;

    if (blockIdx.y >= FY) {
        // ---- amper remainder strips (scalar) ----
        const int y2 = blockIdx.y - FY;
        if (tid >= 256) return;
        if (y2 < 25) {
            const int i = (y2 < 8) ? y2 : 2032 + (y2 - 8);
            const int j = blockIdx.x * 256 + tid;
            if (j >= NE) return;
            amper_point(i, j, Eb, Hxb, Hyb, a0, a1, m01, m11, m21, Eob);
        } else {
            const int c = y2 - 25;                 // 0..16
            const int j = (c < 8) ? c : 2040 + (c - 8);
            const int i = 8 + blockIdx.x * 256 + tid;
            if (i > 2031) return;
            amper_point(i, j, Eb, Hxb, Hyb, a0, a1, m01, m11, m21, Eob);
        }
        return;
    }

    // ---- fused interior tile ----
    const int jb = 8 + blockIdx.x * 256;
    if (jb > 2039) return;                 // uniform: x == 8 exits
    const int i0 = 8 + blockIdx.y * FIT;   // output rows i0..i0+7
    const int ip0 = i0 - 1;                // amper rows ip0..ip0+11

    __shared__ float sE[AIT][260];         // E2 rows i0-1..i0+10, cols jb-1..jb+258

    const int jc = jb - 1 + tid;           // this thread's amper column
    const bool active_a = (tid < 260) && (jc <= 2043);

    const float a1k  = a1 + KB3;
    const float m21k = m21 + KF0;

    if (active_a) {
        float acc[AIT];
#pragma unroll
        for (int k = 0; k < AIT; k++) acc[k] = 0.0f;

        // ---- s1: Hy rows ip0-2 .. ip0+AIT, cols jc-5 .. jc+3 ----
        {
            const float* hy = Hyb + (size_t)(ip0 - 2) * NW + (jc - 5);
#pragma unroll
            for (int rr = 0; rr < AIT + 3; ++rr) {
                const bool uA = (rr <= AIT - 1);
                const bool uB = (rr >= 1 && rr <= AIT);
                const bool uC = (rr >= 2 && rr <= AIT + 1);
                const bool uD = (rr >= 3);
                float c0 = 0.f, c1 = 0.f, c2 = 0.f, c4 = 0.f, c6 = 0.f, c7 = 0.f, c8 = 0.f;
                const float c3 = hy[3];
                const float c5 = hy[5];
                if (uC) { c0 = hy[0]; c1 = hy[1]; c2 = hy[2]; }
                if (uB) { c4 = hy[4]; c6 = hy[6]; c7 = hy[7]; c8 = hy[8]; }
                const float t = a0 * c3 + a1 * c5;
                if (uA) acc[rr]     += t;
                if (uB) acc[rr - 1] += m01 * c3 + m11 * c4 + m21k * c5
                                     + KF1 * c6 + KF2 * c7 + KF3 * c8;
                if (uC) acc[rr - 2] += KB0 * c0 + KB1 * c1 + KB2 * c2
                                     + a1k * c3 + a0 * c5;
                if (uD) acc[rr - 3] += t;
                hy += NW;
            }
        }

        // ---- s2 (subtract): Hx rows ip0-5 .. ip0+AIT+2, cols jc-2 .. jc+1 ----
        {
            const float* hx = Hxb + (size_t)(ip0 - 5) * NH + (jc - 2);
#pragma unroll
            for (int rr = 0; rr < AIT + 8; ++rr) {
                const bool vK0 = (rr <= AIT - 1);
                const bool vK1 = (rr >= 1 && rr <= AIT);
                const bool vK2 = (rr >= 2 && rr <= AIT + 1);
                const bool vA  = (rr >= 3 && rr <= AIT + 2);
                const bool vB  = (rr >= 4 && rr <= AIT + 3);
                const bool vC  = (rr >= 5 && rr <= AIT + 4);
                const bool vD  = (rr >= 6 && rr <= AIT + 5);
                const bool vE  = (rr >= 7 && rr <= AIT + 6);
                const bool vF  = (rr >= 8);
                float d0 = 0.f, d1 = 0.f, d2 = 0.f, d3 = 0.f;
                if (vA | vC) { d0 = hx[0]; d3 = hx[3]; }
                if (vA | vB | vC | vD | vE | vF) d1 = hx[1];
                if (vK0 | vK1 | vK2 | vA | vC) d2 = hx[2];
                if (vK0) acc[rr]     -= KB0 * d2;
                if (vK1) acc[rr - 1] -= KB1 * d2;
                if (vK2) acc[rr - 2] -= KB2 * d2;
                if (vA)  acc[rr - 3] -= a0 * d0 + m01 * d1 + a1k * d2 + a0 * d3;
                if (vB)  acc[rr - 4] -= m11 * d1;
                if (vC)  acc[rr - 5] -= a1 * d0 + m21k * d1 + a0 * d2 + a1 * d3;
                if (vD)  acc[rr - 6] -= KF1 * d1;
                if (vE)  acc[rr - 7] -= KF2 * d1;
                if (vF)  acc[rr - 8] -= KF3 * d1;
                hx += NH;
            }
        }

        // ---- E2 = E + CFL*acc; smem + owned global write ----
        const bool own_col = (tid >= 1) && (tid <= 256) && (jc <= 2039);
        const size_t eoff = (size_t)ip0 * NE + jc;
#pragma unroll
        for (int r = 0; r < AIT; r++) {
            const float e2v = Eb[eoff + (size_t)r * NE] + CFLf * acc[r];
            sE[r][tid] = e2v;
            if (own_col && r >= 1 && r <= FIT)
                Eob[eoff + (size_t)r * NE] = e2v;
        }
    }

    __syncthreads();

    // ---- faraday phase from smem ----
    if (tid < 256) {
        const int j = jb + tid;
        if (j <= 2039) {
            const float m11b = m11 - 1.5f;
            const float m21b = m21 + 2.0f;
            const float a1m2 = a1 - 2.0f;

            float sx[FIT], sy[FIT];
#pragma unroll
            for (int k = 0; k < FIT; k++) { sx[k] = 0.0f; sy[k] = 0.0f; }

#pragma unroll
            for (int rr = 0; rr < FIT + 4; ++rr) {
                const bool w0 = (rr <= FIT - 1);
                const bool w1 = (rr >= 1 && rr <= FIT);
                const bool w2 = (rr >= 2 && rr <= FIT + 1);
                const bool w3 = (rr >= 3 && rr <= FIT + 2);
                const bool w4 = (rr >= 4);
                const float e0 = sE[rr][tid + 0];
                const float e1 = sE[rr][tid + 1];
                const float e2 = sE[rr][tid + 2];
                const float e3 = sE[rr][tid + 3];
                const float e4 = sE[rr][tid + 4];

                const float ty = a0 * e1 + a1 * e3;
                if (w0) { sx[rr] += 0.5f * e2; sy[rr] += ty; }
                if (w1) {
                    sx[rr - 1] += a0 * e0 + m01 * e1 + a1m2 * e2 + a0 * e3;
                    sy[rr - 1] += m01 * e1 + m11b * e2 + m21b * e3 - 0.5f * e4;
                }
                if (w2) {
                    sx[rr - 2] += m11b * e1 + 1.5f * e2;
                    sy[rr - 2] += 0.5f * e0 + a1m2 * e1 + 1.5f * e2 + a0 * e3;
                }
                if (w3) {
                    sx[rr - 3] += a1 * e0 + m21b * e1 + a0 * e2 + a1 * e3;
                    sy[rr - 3] += ty;
                }
                if (w4) sx[rr - 4] -= 0.5f * e1;
            }

            const size_t offx = (size_t)i0 * NH + j;
            const size_t offy = (size_t)i0 * NW + j;
#pragma unroll
            for (int k = 0; k < FIT; k++) {
                Hxob[offx + (size_t)k * NH] = Hxb[offx + (size_t)k * NH] - CFLf * sx[k];
                Hyob[offy + (size_t)k * NW] = Hyb[offy + (size_t)k * NW] + CFLf * sy[k];
            }
        }
    }
}

// ===========================================================================
// Faraday remainder: rows {0-7, 2032-2047} all j; cols {0-7, 2040-2047} for
// rows 8-2031. Runs AFTER fused kernel (needs complete E2).
// ===========================================================================
__global__ __launch_bounds__(256)
void faraday_rem_kernel(const float* __restrict__ E,
                        const float* __restrict__ Hx,
                        const float* __restrict__ Hy,
                        const float* __restrict__ pb,
                        const float* __restrict__ pd,
                        const float* __restrict__ pg,
                        float* __restrict__ Hxo,
                        float* __restrict__ Hyo) {
    const int b = blockIdx.z;
    float a0, a1, m01, m11, m21;
    load_M(*pb, *pd, *pg, a0, a1, m01, m11, m21);

    const float* Eb  = E  + (size_t)b * NE * NE;
    const float* Hxb = Hx + (size_t)b * NW * NH;
    const float* Hyb = Hy + (size_t)b * NH * NW;
    float* Hxob = Hxo + (size_t)b * NW * NH;
    float* Hyob = Hyo + (size_t)b * NH * NW;

    const int y = blockIdx.y;
    if (y < 24) {
        const int i = (y < 8) ? y : 2032 + (y - 8);
        const int j = blockIdx.x * 256 + threadIdx.x;
        if (j >= NH) return;
        faraday_point(i, j, Eb, Hxb, Hyb, a0, a1, m01, m11, m21, Hxob, Hyob);
    } else {
        const int c = y - 24;                  // 0..15
        const int j = (c < 8) ? c : 2040 + (c - 8);
        const int i = 8 + blockIdx.x * 256 + threadIdx.x;
        if (i > 2031) return;
        faraday_point(i, j, Eb, Hxb, Hyb, a0, a1, m01, m11, m21, Hxob, Hyob);
    }
}

// ===========================================================================
extern "C" void kernel_launch(void* const* d_in, const int* in_sizes, int n_in,
                              void* d_out, int out_size) {
    const float* E0  = (const float*)d_in[0];
    const float* Hx0 = (const float*)d_in[1];
    const float* Hy0 = (const float*)d_in[2];
    const float* pb  = (const float*)d_in[3];
    const float* pd  = (const float*)d_in[4];
    const float* pg  = (const float*)d_in[5];

    const int B = in_sizes[0] / (NE * NE);

    const size_t nE  = (size_t)B * NE * NE;
    const size_t nHx = (size_t)B * NW * NH;
    const size_t nHy = (size_t)B * NH * NW;

    float* out = (float*)d_out;
    float* E2  = out;
    float* Hx2 = E2 + nE;
    float* Hy2 = Hx2 + nHx;
    float* E3  = Hy2 + nHy;
    float* Hx3 = E3 + nE;
    float* Hy3 = Hx3 + nHx;
    float* E4  = Hy3 + nHy;
    float* Hx4 = E4 + nE;
    float* Hy4 = Hx4 + nHx;

    dim3 gF(9, FY + A_STRIP_Y, B);   // fused kernel (x=9 for 2049-wide strips)
    dim3 gR(8, 40, B);               // faraday remainder

    const float* Ein  = E0;
    const float* Hxin = Hx0;
    const float* Hyin = Hy0;
    float* Eouts[3]  = {E2, E3, E4};
    float* Hxouts[3] = {Hx2, Hx3, Hx4};
    float* Hyouts[3] = {Hy2, Hy3, Hy4};

    for (int s = 0; s < 3; s++) {
        fused_step_kernel<<<gF, 288>>>(Ein, Hxin, Hyin, pb, pd, pg,
                                       Eouts[s], Hxouts[s], Hyouts[s]);
        faraday_rem_kernel<<<gR, 256>>>(Eouts[s], Hxin, Hyin, pb, pd, pg,
                                        Hxouts[s], Hyouts[s]);
        Ein = Eouts[s]; Hxin = Hxouts[s]; Hyin = Hyouts[s];
    }
}

// round 13
// speedup vs baseline: 1.0681x; 1.0088x over previous
#include <cuda_runtime.h>

#define NE 2049   // E is NE x NE
#define NH 2048   // Hx cols / Hy rows
#define NW 2047   // Hx rows / Hy cols
#define CFLf 0.35f

#define KF0 (-11.0f/6.0f)
#define KF1 (3.0f)
#define KF2 (-1.5f)
#define KF3 (1.0f/3.0f)
#define KB0 (-1.0f/3.0f)
#define KB1 (1.5f)
#define KB2 (-3.0f)
#define KB3 (11.0f/6.0f)

#define IT 8
#define A_INT_Y 254   // amper interior: i0 = 5 + 8*y, i in [5,2036]
#define A_BND_Y 27    // 17 row strips + 10 col strips
#define F_INT_Y 255   // faraday interior: i0 = 2 + 8*y, i in [2,2041]
#define F_BND_Y 13    // 8 row strips + 5 col strips

__device__ __forceinline__ void load_M(float beta, float delta, float gamma,
                                       float& a0, float& a1,
                                       float& m01, float& m11, float& m21) {
    a0  = -0.25f * beta + 0.1f * gamma;
    a1  =  0.25f * beta - 0.1f * gamma;
    m01 =  0.25f * beta + delta - 0.5f - 0.1f * gamma;
    m11 = -2.0f * delta;
    m21 = -0.25f * beta + delta + 0.5f + 0.1f * gamma;
}

// ===========================================================================
// Scalar point functions (verified) — boundary strips.
// ===========================================================================
__device__ void amper_point(int i, int j,
                            const float* __restrict__ Eb,
                            const float* __restrict__ Hxb,
                            const float* __restrict__ Hyb,
                            float a0, float a1, float m01, float m11, float m21,
                            float* __restrict__ Eob) {
    const bool ic = (i >= 2 && i <= NE - 3);
    const bool jc = (j >= 2 && j <= NE - 3);
    float s1 = 0.0f, s2 = 0.0f;

    if (ic && jc) {
        const float* r0 = Hyb + (size_t)(i - 2) * NW + (j - 2);
        const float* r1 = r0 + NW;
        const float* r2 = r1 + NW;
        const float* r3 = r2 + NW;
        s1 += a0  * r0[0] + a1  * r0[2]
            + m01 * r1[0] + m11 * r1[1] + m21 * r1[2]
            + a1  * r2[0] + a0  * r2[2]
            + a0  * r3[0] + a1  * r3[2];
        const float* x0 = Hxb + (size_t)(i - 2) * NH + (j - 2);
        const float* x1 = x0 + NH;
        const float* x2 = x1 + NH;
        s2 += a0 * x0[0] + m01 * x0[1] + a1 * x0[2] + a0 * x0[3]
            + m11 * x1[1]
            + a1 * x2[0] + m21 * x2[1] + a0 * x2[2] + a1 * x2[3];
    }
    if (i >= 1 && j <= NE - 6) {
        const float* r = Hyb + (size_t)(i - 1) * NW + j;
        s1 += KF0 * r[0] + KF1 * r[1] + KF2 * r[2] + KF3 * r[3];
    }
    if (i <= NE - 2 && j >= 5) {
        const float* r = Hyb + (size_t)i * NW + (j - 5);
        s1 += KB0 * r[0] + KB1 * r[1] + KB2 * r[2] + KB3 * r[3];
    }
    if (ic && (j == 1 || j == 2)) {
        const float* r = Hyb + (size_t)(i - 1) * NW + (j - 1);
        s1 += -r[0] + 3.0f * r[1] - 3.0f * r[2] + r[3];
    }
    if (ic && (j == NE - 3 || j == NE - 2)) {
        const float* r = Hyb + (size_t)i * NW + (j - 4);
        s1 += r[0] - 3.0f * r[1] + 3.0f * r[2] - r[3];
    }
    if (i <= NE - 6 && j >= 1) {
        const float* x = Hxb + (size_t)i * NH + (j - 1);
        s2 += KF0 * x[0] + KF1 * x[NH] + KF2 * x[2 * NH] + KF3 * x[3 * NH];
    }
    if (i >= 5 && j <= NE - 2) {
        const float* x = Hxb + (size_t)(i - 5) * NH + j;
        s2 += KB0 * x[0] + KB1 * x[NH] + KB2 * x[2 * NH] + KB3 * x[3 * NH];
    }
    if ((i == 1 || i == 2) && jc) {
        const float* x = Hxb + (size_t)(i - 1) * NH + (j - 1);
        s2 += -x[0] + 3.0f * x[NH] - 3.0f * x[2 * NH] + x[3 * NH];
    }
    if ((i == NE - 3 || i == NE - 2) && jc) {
        const float* x = Hxb + (size_t)(i - 4) * NH + j;
        s2 += x[0] - 3.0f * x[NH] + 3.0f * x[2 * NH] - x[3 * NH];
    }
    Eob[(size_t)i * NE + j] = Eb[(size_t)i * NE + j] + CFLf * (s1 - s2);
}

__device__ void faraday_point(int i, int j,
                              const float* __restrict__ Eb,
                              const float* __restrict__ Hxb,
                              const float* __restrict__ Hyb,
                              float a0, float a1, float m01, float m11, float m21,
                              float* __restrict__ Hxob,
                              float* __restrict__ Hyob) {
    if (i < NW && j < NH) {
        float s3 = 0.0f;
        if (j >= 1 && j <= NH - 2) {
            const float* e0 = Eb + (size_t)i * NE + (j - 1);
            const float* e1 = e0 + NE;
            const float* e2 = e1 + NE;
            s3 += a0 * e0[0] + m01 * e0[1] + a1 * e0[2] + a0 * e0[3]
                + m11 * e1[1]
                + a1 * e2[0] + m21 * e2[1] + a0 * e2[2] + a1 * e2[3];
        }
        if (i <= NH - 4) {
            const float* e = Eb + (size_t)(i + 1) * NE + j;
            s3 += -1.5f * e[0] + 2.0f * e[NE] - 0.5f * e[2 * NE];
        }
        if (i >= 2) {
            const float* e = Eb + (size_t)(i - 1) * NE + (j + 1);
            s3 += 0.5f * e[0] - 2.0f * e[NE] + 1.5f * e[2 * NE];
        }
        const size_t off = (size_t)i * NH + j;
        Hxob[off] = Hxb[off] - CFLf * s3;
    }
    if (i < NH && j < NW) {
        float s4 = 0.0f;
        if (i >= 1 && i <= NH - 2) {
            const float* e0 = Eb + (size_t)(i - 1) * NE + j;
            const float* e1 = e0 + NE;
            const float* e2 = e1 + NE;
            const float* e3 = e2 + NE;
            s4 += a0  * e0[0] + a1  * e0[2]
                + m01 * e1[0] + m11 * e1[1] + m21 * e1[2]
                + a1  * e2[0] + a0  * e2[2]
                + a0  * e3[0] + a1  * e3[2];
        }
        if (j <= NH - 4) {
            const float* e = Eb + (size_t)i * NE + (j + 1);
            s4 += -1.5f * e[0] + 2.0f * e[1] - 0.5f * e[2];
        }
        if (j >= 2) {
            const float* e = Eb + (size_t)(i + 1) * NE + (j - 1);
            s4 += 0.5f * e[0] - 2.0f * e[1] + 1.5f * e[2];
        }
        const size_t off = (size_t)i * NW + j;
        Hyob[off] = Hyb[off] + CFLf * s4;
    }
}

// ===========================================================================
// Fused amper: interior (IT=8, ILP=2 columns/thread) + boundary strips.
// ===========================================================================
__global__ __launch_bounds__(256)
void amper_kernel(const float* __restrict__ E,
                  const float* __restrict__ Hx,
                  const float* __restrict__ Hy,
                  const float* __restrict__ pb,
                  const float* __restrict__ pd,
                  const float* __restrict__ pg,
                  float* __restrict__ Eo) {
    const int b = blockIdx.z;
    float a0, a1, m01, m11, m21;
    load_M(*pb, *pd, *pg, a0, a1, m01, m11, m21);

    const float* Eb  = E  + (size_t)b * NE * NE;
    const float* Hxb = Hx + (size_t)b * NW * NH;
    const float* Hyb = Hy + (size_t)b * NH * NW;
    float* Eob = Eo + (size_t)b * NE * NE;

    if (blockIdx.y >= A_INT_Y) {
        const int y = blockIdx.y - A_INT_Y;
        if (y < 17) {
            const int i = (y < 5) ? y : 2037 + (y - 5);
            const int j = blockIdx.x * 256 + threadIdx.x;
            if (j >= NE) return;
            amper_point(i, j, Eb, Hxb, Hyb, a0, a1, m01, m11, m21, Eob);
        } else {
            const int c = y - 17;
            const int j = (c < 5) ? c : 2044 + (c - 5);
            const int i = 5 + blockIdx.x * 256 + threadIdx.x;
            if (i > 2036) return;
            amper_point(i, j, Eb, Hxb, Hyb, a0, a1, m01, m11, m21, Eob);
        }
        return;
    }

    // ---- interior: i0 = 5 + 8*y; 4 blocks x 512 cols; j in [5, 2043] ----
    if (blockIdx.x >= 4) return;
    const int jb = 5 + blockIdx.x * 512;
    const int i0 = 5 + blockIdx.y * IT;
    const int jA = jb + threadIdx.x;          // always <= 1796, valid
    const int jBr = jA + 256;                 // may exceed 2043
    const bool vB = (jBr <= 2043);
    const int jB = vB ? jBr : 2043;           // clamp for in-bounds loads

    const float a1k  = a1 + KB3;
    const float m21k = m21 + KF0;

    float acc[2][IT];
#pragma unroll
    for (int p = 0; p < 2; p++)
#pragma unroll
        for (int k = 0; k < IT; k++) acc[p][k] = 0.0f;

    // ---- s1: Hy rows i0-2 .. i0+8, window cols j-5 .. j+3 ----
    {
        const float* hy0 = Hyb + (size_t)(i0 - 2) * NW + (jA - 5);
        const float* hy1 = Hyb + (size_t)(i0 - 2) * NW + (jB - 5);
#pragma unroll
        for (int rr = 0; rr < IT + 3; ++rr) {
            const bool uA = (rr <= IT - 1);
            const bool uB = (rr >= 1 && rr <= IT);
            const bool uC = (rr >= 2 && rr <= IT + 1);
            const bool uD = (rr >= 3);
            const float* hp[2] = {hy0, hy1};
#pragma unroll
            for (int p = 0; p < 2; p++) {
                const float* hy = hp[p];
                float c0 = 0.f, c1 = 0.f, c2 = 0.f, c4 = 0.f, c6 = 0.f, c7 = 0.f, c8 = 0.f;
                const float c3 = hy[3];
                const float c5 = hy[5];
                if (uC) { c0 = hy[0]; c1 = hy[1]; c2 = hy[2]; }
                if (uB) { c4 = hy[4]; c6 = hy[6]; c7 = hy[7]; c8 = hy[8]; }
                const float t = a0 * c3 + a1 * c5;
                if (uA) acc[p][rr]     += t;
                if (uB) acc[p][rr - 1] += m01 * c3 + m11 * c4 + m21k * c5
                                        + KF1 * c6 + KF2 * c7 + KF3 * c8;
                if (uC) acc[p][rr - 2] += KB0 * c0 + KB1 * c1 + KB2 * c2
                                        + a1k * c3 + a0 * c5;
                if (uD) acc[p][rr - 3] += t;
            }
            hy0 += NW; hy1 += NW;
        }
    }

    // ---- s2 (subtract): Hx rows i0-5 .. i0+10, window cols j-2 .. j+1 ----
    {
        const float* hx0 = Hxb + (size_t)(i0 - 5) * NH + (jA - 2);
        const float* hx1 = Hxb + (size_t)(i0 - 5) * NH + (jB - 2);
#pragma unroll
        for (int rr = 0; rr < IT + 8; ++rr) {
            const bool vK0 = (rr <= IT - 1);
            const bool vK1 = (rr >= 1 && rr <= IT);
            const bool vK2 = (rr >= 2 && rr <= IT + 1);
            const bool vA  = (rr >= 3 && rr <= IT + 2);
            const bool vBt = (rr >= 4 && rr <= IT + 3);
            const bool vC  = (rr >= 5 && rr <= IT + 4);
            const bool vD  = (rr >= 6 && rr <= IT + 5);
            const bool vE  = (rr >= 7 && rr <= IT + 6);
            const bool vF  = (rr >= 8);
            const float* hp[2] = {hx0, hx1};
#pragma unroll
            for (int p = 0; p < 2; p++) {
                const float* hx = hp[p];
                float d0 = 0.f, d1 = 0.f, d2 = 0.f, d3 = 0.f;
                if (vA | vC) { d0 = hx[0]; d3 = hx[3]; }
                if (vA | vBt | vC | vD | vE | vF) d1 = hx[1];
                if (vK0 | vK1 | vK2 | vA | vC) d2 = hx[2];
                if (vK0) acc[p][rr]     -= KB0 * d2;
                if (vK1) acc[p][rr - 1] -= KB1 * d2;
                if (vK2) acc[p][rr - 2] -= KB2 * d2;
                if (vA)  acc[p][rr - 3] -= a0 * d0 + m01 * d1 + a1k * d2 + a0 * d3;
                if (vBt) acc[p][rr - 4] -= m11 * d1;
                if (vC)  acc[p][rr - 5] -= a1 * d0 + m21k * d1 + a0 * d2 + a1 * d3;
                if (vD)  acc[p][rr - 6] -= KF1 * d1;
                if (vE)  acc[p][rr - 7] -= KF2 * d1;
                if (vF)  acc[p][rr - 8] -= KF3 * d1;
            }
            hx0 += NH; hx1 += NH;
        }
    }

    const size_t offA = (size_t)i0 * NE + jA;
#pragma unroll
    for (int k = 0; k < IT; k++)
        Eob[offA + (size_t)k * NE] = Eb[offA + (size_t)k * NE] + CFLf * acc[0][k];
    if (vB) {
        const size_t offB = (size_t)i0 * NE + jB;
#pragma unroll
        for (int k = 0; k < IT; k++)
            Eob[offB + (size_t)k * NE] = Eb[offB + (size_t)k * NE] + CFLf * acc[1][k];
    }
}

// ===========================================================================
// Fused faraday (Hx+Hy): interior (IT=8, ILP=2 columns) + boundary strips.
// ===========================================================================
__global__ __launch_bounds__(256)
void faraday_kernel(const float* __restrict__ E,
                    const float* __restrict__ Hx,
                    const float* __restrict__ Hy,
                    const float* __restrict__ pb,
                    const float* __restrict__ pd,
                    const float* __restrict__ pg,
                    float* __restrict__ Hxo,
                    float* __restrict__ Hyo) {
    const int b = blockIdx.z;
    float a0, a1, m01, m11, m21;
    load_M(*pb, *pd, *pg, a0, a1, m01, m11, m21);

    const float* Eb  = E  + (size_t)b * NE * NE;
    const float* Hxb = Hx + (size_t)b * NW * NH;
    const float* Hyb = Hy + (size_t)b * NH * NW;
    float* Hxob = Hxo + (size_t)b * NW * NH;
    float* Hyob = Hyo + (size_t)b * NH * NW;

    if (blockIdx.y >= F_INT_Y) {
        const int y = blockIdx.y - F_INT_Y;
        if (y < 8) {
            const int i = (y < 2) ? y : 2042 + (y - 2);
            const int j = blockIdx.x * 256 + threadIdx.x;
            if (j >= NH) return;
            faraday_point(i, j, Eb, Hxb, Hyb, a0, a1, m01, m11, m21, Hxob, Hyob);
        } else {
            const int c = y - 8;
            const int j = (c < 2) ? c : 2045 + (c - 2);
            const int i = 2 + blockIdx.x * 256 + threadIdx.x;
            if (i > 2041) return;
            faraday_point(i, j, Eb, Hxb, Hyb, a0, a1, m01, m11, m21, Hxob, Hyob);
        }
        return;
    }

    // ---- interior: i0 = 2 + 8*y; 4 blocks x 512 cols; j in [2, 2044] ----
    if (blockIdx.x >= 4) return;
    const int jb = 2 + blockIdx.x * 512;
    const int i0 = 2 + blockIdx.y * IT;
    const int jA = jb + threadIdx.x;          // always <= 1793, valid
    const int jBr = jA + 256;
    const bool vB = (jBr <= 2044);
    const int jB = vB ? jBr : 2044;

    const float m11b = m11 - 1.5f;
    const float m21b = m21 + 2.0f;
    const float a1m2 = a1 - 2.0f;

    float sx[2][IT], sy[2][IT];
#pragma unroll
    for (int p = 0; p < 2; p++)
#pragma unroll
        for (int k = 0; k < IT; k++) { sx[p][k] = 0.0f; sy[p][k] = 0.0f; }

    {
        const float* ep0 = Eb + (size_t)(i0 - 1) * NE + (jA - 1);
        const float* ep1 = Eb + (size_t)(i0 - 1) * NE + (jB - 1);
#pragma unroll
        for (int rr = 0; rr < IT + 4; ++rr) {
            const bool w0 = (rr <= IT - 1);
            const bool w1 = (rr >= 1 && rr <= IT);
            const bool w2 = (rr >= 2 && rr <= IT + 1);
            const bool w3 = (rr >= 3 && rr <= IT + 2);
            const bool w4 = (rr >= 4);
            const float* epp[2] = {ep0, ep1};
#pragma unroll
            for (int p = 0; p < 2; p++) {
                const float* ep = epp[p];
                float e0 = 0.f, e2 = 0.f, e3 = 0.f, e4 = 0.f;
                const float e1 = ep[1];
                if (w1 | w2 | w3) e0 = ep[0];
                if (w0 | w1 | w2 | w3) { e2 = ep[2]; e3 = ep[3]; }
                if (w1) e4 = ep[4];

                const float ty = a0 * e1 + a1 * e3;
                if (w0) { sx[p][rr] += 0.5f * e2; sy[p][rr] += ty; }
                if (w1) {
                    sx[p][rr - 1] += a0 * e0 + m01 * e1 + a1m2 * e2 + a0 * e3;
                    sy[p][rr - 1] += m01 * e1 + m11b * e2 + m21b * e3 - 0.5f * e4;
                }
                if (w2) {
                    sx[p][rr - 2] += m11b * e1 + 1.5f * e2;
                    sy[p][rr - 2] += 0.5f * e0 + a1m2 * e1 + 1.5f * e2 + a0 * e3;
                }
                if (w3) {
                    sx[p][rr - 3] += a1 * e0 + m21b * e1 + a0 * e2 + a1 * e3;
                    sy[p][rr - 3] += ty;
                }
                if (w4) sx[p][rr - 4] -= 0.5f * e1;
            }
            ep0 += NE; ep1 += NE;
        }
    }

    {
        const size_t offx = (size_t)i0 * NH + jA;
        const size_t offy = (size_t)i0 * NW + jA;
#pragma unroll
        for (int k = 0; k < IT; k++) {
            Hxob[offx + (size_t)k * NH] = Hxb[offx + (size_t)k * NH] - CFLf * sx[0][k];
            Hyob[offy + (size_t)k * NW] = Hyb[offy + (size_t)k * NW] + CFLf * sy[0][k];
        }
    }
    if (vB) {
        const size_t offx = (size_t)i0 * NH + jB;
        const size_t offy = (size_t)i0 * NW + jB;
#pragma unroll
        for (int k = 0; k < IT; k++) {
            Hxob[offx + (size_t)k * NH] = Hxb[offx + (size_t)k * NH] - CFLf * sx[1][k];
            Hyob[offy + (size_t)k * NW] = Hyb[offy + (size_t)k * NW] + CFLf * sy[1][k];
        }
    }
}

// ===========================================================================
extern "C" void kernel_launch(void* const* d_in, const int* in_sizes, int n_in,
                              void* d_out, int out_size) {
    const float* E0  = (const float*)d_in[0];
    const float* Hx0 = (const float*)d_in[1];
    const float* Hy0 = (const float*)d_in[2];
    const float* pb  = (const float*)d_in[3];
    const float* pd  = (const float*)d_in[4];
    const float* pg  = (const float*)d_in[5];

    const int B = in_sizes[0] / (NE * NE);

    const size_t nE  = (size_t)B * NE * NE;
    const size_t nHx = (size_t)B * NW * NH;
    const size_t nHy = (size_t)B * NH * NW;

    float* out = (float*)d_out;
    float* E2  = out;
    float* Hx2 = E2 + nE;
    float* Hy2 = Hx2 + nHx;
    float* E3  = Hy2 + nHy;
    float* Hx3 = E3 + nE;
    float* Hy3 = Hx3 + nHx;
    float* E4  = Hy3 + nHy;
    float* Hx4 = E4 + nE;
    float* Hy4 = Hx4 + nHx;

    dim3 blk(256);
    dim3 gA(9, A_INT_Y + A_BND_Y, B);  // x=9 for 2049-wide boundary rows
    dim3 gF(8, F_INT_Y + F_BND_Y, B);

    const float* Ein  = E0;
    const float* Hxin = Hx0;
    const float* Hyin = Hy0;
    float* Eouts[3]  = {E2, E3, E4};
    float* Hxouts[3] = {Hx2, Hx3, Hx4};
    float* Hyouts[3] = {Hy2, Hy3, Hy4};

    for (int s = 0; s < 3; s++) {
        amper_kernel<<<gA, blk>>>(Ein, Hxin, Hyin, pb, pd, pg, Eouts[s]);
        faraday_kernel<<<gF, blk>>>(Eouts[s], Hxin, Hyin, pb, pd, pg,
                                    Hxouts[s], Hyouts[s]);
        Ein = Eouts[s]; Hxin = Hxouts[s]; Hyin = Hyouts[s];
    }
}

// round 14
// speedup vs baseline: 1.1899x; 1.1140x over previous
#include <cuda_runtime.h>

#define NE 2049   // E is NE x NE
#define NH 2048   // Hx cols / Hy rows
#define NW 2047   // Hx rows / Hy cols
#define CFLf 0.35f

#define KF0 (-11.0f/6.0f)
#define KF1 (3.0f)
#define KF2 (-1.5f)
#define KF3 (1.0f/3.0f)
#define KB0 (-1.0f/3.0f)
#define KB1 (1.5f)
#define KB2 (-3.0f)
#define KB3 (11.0f/6.0f)

#define IT 8
#define A_INT_Y 254   // amper interior: i0 = 5 + 8*y, i in [5,2036]
#define A_BND_Y 27    // 17 row strips + 10 col strips
#define F_INT_Y 255   // faraday interior: i0 = 2 + 8*y, i in [2,2041]
#define F_BND_Y 13    // 8 row strips + 5 col strips

__device__ __forceinline__ void load_M(float beta, float delta, float gamma,
                                       float& a0, float& a1,
                                       float& m01, float& m11, float& m21) {
    a0  = -0.25f * beta + 0.1f * gamma;
    a1  =  0.25f * beta - 0.1f * gamma;
    m01 =  0.25f * beta + delta - 0.5f - 0.1f * gamma;
    m11 = -2.0f * delta;
    m21 = -0.25f * beta + delta + 0.5f + 0.1f * gamma;
}

// ===========================================================================
// Scalar point functions (verified) — boundary strips.
// ===========================================================================
__device__ void amper_point(int i, int j,
                            const float* __restrict__ Eb,
                            const float* __restrict__ Hxb,
                            const float* __restrict__ Hyb,
                            float a0, float a1, float m01, float m11, float m21,
                            float* __restrict__ Eob) {
    const bool ic = (i >= 2 && i <= NE - 3);
    const bool jc = (j >= 2 && j <= NE - 3);
    float s1 = 0.0f, s2 = 0.0f;

    if (ic && jc) {
        const float* r0 = Hyb + (size_t)(i - 2) * NW + (j - 2);
        const float* r1 = r0 + NW;
        const float* r2 = r1 + NW;
        const float* r3 = r2 + NW;
        s1 += a0  * r0[0] + a1  * r0[2]
            + m01 * r1[0] + m11 * r1[1] + m21 * r1[2]
            + a1  * r2[0] + a0  * r2[2]
            + a0  * r3[0] + a1  * r3[2];
        const float* x0 = Hxb + (size_t)(i - 2) * NH + (j - 2);
        const float* x1 = x0 + NH;
        const float* x2 = x1 + NH;
        s2 += a0 * x0[0] + m01 * x0[1] + a1 * x0[2] + a0 * x0[3]
            + m11 * x1[1]
            + a1 * x2[0] + m21 * x2[1] + a0 * x2[2] + a1 * x2[3];
    }
    if (i >= 1 && j <= NE - 6) {
        const float* r = Hyb + (size_t)(i - 1) * NW + j;
        s1 += KF0 * r[0] + KF1 * r[1] + KF2 * r[2] + KF3 * r[3];
    }
    if (i <= NE - 2 && j >= 5) {
        const float* r = Hyb + (size_t)i * NW + (j - 5);
        s1 += KB0 * r[0] + KB1 * r[1] + KB2 * r[2] + KB3 * r[3];
    }
    if (ic && (j == 1 || j == 2)) {
        const float* r = Hyb + (size_t)(i - 1) * NW + (j - 1);
        s1 += -r[0] + 3.0f * r[1] - 3.0f * r[2] + r[3];
    }
    if (ic && (j == NE - 3 || j == NE - 2)) {
        const float* r = Hyb + (size_t)i * NW + (j - 4);
        s1 += r[0] - 3.0f * r[1] + 3.0f * r[2] - r[3];
    }
    if (i <= NE - 6 && j >= 1) {
        const float* x = Hxb + (size_t)i * NH + (j - 1);
        s2 += KF0 * x[0] + KF1 * x[NH] + KF2 * x[2 * NH] + KF3 * x[3 * NH];
    }
    if (i >= 5 && j <= NE - 2) {
        const float* x = Hxb + (size_t)(i - 5) * NH + j;
        s2 += KB0 * x[0] + KB1 * x[NH] + KB2 * x[2 * NH] + KB3 * x[3 * NH];
    }
    if ((i == 1 || i == 2) && jc) {
        const float* x = Hxb + (size_t)(i - 1) * NH + (j - 1);
        s2 += -x[0] + 3.0f * x[NH] - 3.0f * x[2 * NH] + x[3 * NH];
    }
    if ((i == NE - 3 || i == NE - 2) && jc) {
        const float* x = Hxb + (size_t)(i - 4) * NH + j;
        s2 += x[0] - 3.0f * x[NH] + 3.0f * x[2 * NH] - x[3 * NH];
    }
    Eob[(size_t)i * NE + j] = Eb[(size_t)i * NE + j] + CFLf * (s1 - s2);
}

__device__ void faraday_point(int i, int j,
                              const float* __restrict__ Eb,
                              const float* __restrict__ Hxb,
                              const float* __restrict__ Hyb,
                              float a0, float a1, float m01, float m11, float m21,
                              float* __restrict__ Hxob,
                              float* __restrict__ Hyob) {
    if (i < NW && j < NH) {
        float s3 = 0.0f;
        if (j >= 1 && j <= NH - 2) {
            const float* e0 = Eb + (size_t)i * NE + (j - 1);
            const float* e1 = e0 + NE;
            const float* e2 = e1 + NE;
            s3 += a0 * e0[0] + m01 * e0[1] + a1 * e0[2] + a0 * e0[3]
                + m11 * e1[1]
                + a1 * e2[0] + m21 * e2[1] + a0 * e2[2] + a1 * e2[3];
        }
        if (i <= NH - 4) {
            const float* e = Eb + (size_t)(i + 1) * NE + j;
            s3 += -1.5f * e[0] + 2.0f * e[NE] - 0.5f * e[2 * NE];
        }
        if (i >= 2) {
            const float* e = Eb + (size_t)(i - 1) * NE + (j + 1);
            s3 += 0.5f * e[0] - 2.0f * e[NE] + 1.5f * e[2 * NE];
        }
        const size_t off = (size_t)i * NH + j;
        Hxob[off] = Hxb[off] - CFLf * s3;
    }
    if (i < NH && j < NW) {
        float s4 = 0.0f;
        if (i >= 1 && i <= NH - 2) {
            const float* e0 = Eb + (size_t)(i - 1) * NE + j;
            const float* e1 = e0 + NE;
            const float* e2 = e1 + NE;
            const float* e3 = e2 + NE;
            s4 += a0  * e0[0] + a1  * e0[2]
                + m01 * e1[0] + m11 * e1[1] + m21 * e1[2]
                + a1  * e2[0] + a0  * e2[2]
                + a0  * e3[0] + a1  * e3[2];
        }
        if (j <= NH - 4) {
            const float* e = Eb + (size_t)i * NE + (j + 1);
            s4 += -1.5f * e[0] + 2.0f * e[1] - 0.5f * e[2];
        }
        if (j >= 2) {
            const float* e = Eb + (size_t)(i + 1) * NE + (j - 1);
            s4 += 0.5f * e[0] - 2.0f * e[1] + 1.5f * e[2];
        }
        const size_t off = (size_t)i * NW + j;
        Hyob[off] = Hyb[off] + CFLf * s4;
    }
}

// ===========================================================================
// Fused amper: interior slices (blockIdx.y < A_INT_Y) + boundary strips.
// ===========================================================================
__global__ __launch_bounds__(256)
void amper_kernel(const float* __restrict__ E,
                  const float* __restrict__ Hx,
                  const float* __restrict__ Hy,
                  const float* __restrict__ pb,
                  const float* __restrict__ pd,
                  const float* __restrict__ pg,
                  float* __restrict__ Eo) {
    const int b = blockIdx.z;
    float a0, a1, m01, m11, m21;
    load_M(*pb, *pd, *pg, a0, a1, m01, m11, m21);

    const float* Eb  = E  + (size_t)b * NE * NE;
    const float* Hxb = Hx + (size_t)b * NW * NH;
    const float* Hyb = Hy + (size_t)b * NH * NW;
    float* Eob = Eo + (size_t)b * NE * NE;

    if (blockIdx.y >= A_INT_Y) {
        // ---- boundary strips ----
        const int y = blockIdx.y - A_INT_Y;
        if (y < 17) {
            const int i = (y < 5) ? y : 2037 + (y - 5);
            const int j = blockIdx.x * 256 + threadIdx.x;
            if (j >= NE) return;
            amper_point(i, j, Eb, Hxb, Hyb, a0, a1, m01, m11, m21, Eob);
        } else {
            const int c = y - 17;
            const int j = (c < 5) ? c : 2044 + (c - 5);
            const int i = 5 + blockIdx.x * 256 + threadIdx.x;
            if (i > 2036) return;
            amper_point(i, j, Eb, Hxb, Hyb, a0, a1, m01, m11, m21, Eob);
        }
        return;
    }

    // ---- interior: i0 = 5 + 8*y, j in [5, 2043] ----
    const int j = 5 + blockIdx.x * 256 + threadIdx.x;
    if (j > 2043) return;
    const int i0 = 5 + blockIdx.y * IT;

    const float a1k  = a1 + KB3;
    const float m21k = m21 + KF0;

    float acc[IT];
#pragma unroll
    for (int k = 0; k < IT; k++) acc[k] = 0.0f;

    // ---- s1: Hy rows r = i0-2 .. i0+8, cols j-5 .. j+3 ----
    {
        const float* hy = Hyb + (size_t)(i0 - 2) * NW + (j - 5);
#pragma unroll
        for (int rr = 0; rr < IT + 3; ++rr) {
            const bool uA = (rr <= IT - 1);
            const bool uB = (rr >= 1 && rr <= IT);
            const bool uC = (rr >= 2 && rr <= IT + 1);
            const bool uD = (rr >= 3);
            float c0 = 0.f, c1 = 0.f, c2 = 0.f, c4 = 0.f, c6 = 0.f, c7 = 0.f, c8 = 0.f;
            const float c3 = hy[3];
            const float c5 = hy[5];
            if (uC) { c0 = hy[0]; c1 = hy[1]; c2 = hy[2]; }
            if (uB) { c4 = hy[4]; c6 = hy[6]; c7 = hy[7]; c8 = hy[8]; }
            const float t = a0 * c3 + a1 * c5;
            if (uA) acc[rr]     += t;
            if (uB) acc[rr - 1] += m01 * c3 + m11 * c4 + m21k * c5
                                 + KF1 * c6 + KF2 * c7 + KF3 * c8;
            if (uC) acc[rr - 2] += KB0 * c0 + KB1 * c1 + KB2 * c2
                                 + a1k * c3 + a0 * c5;
            if (uD) acc[rr - 3] += t;
            hy += NW;
        }
    }

    // ---- s2 (subtract): Hx rows r = i0-5 .. i0+10, cols j-2 .. j+1 ----
    {
        const float* hx = Hxb + (size_t)(i0 - 5) * NH + (j - 2);
#pragma unroll
        for (int rr = 0; rr < IT + 8; ++rr) {
            const bool vK0 = (rr <= IT - 1);
            const bool vK1 = (rr >= 1 && rr <= IT);
            const bool vK2 = (rr >= 2 && rr <= IT + 1);
            const bool vA  = (rr >= 3 && rr <= IT + 2);
            const bool vB  = (rr >= 4 && rr <= IT + 3);
            const bool vC  = (rr >= 5 && rr <= IT + 4);
            const bool vD  = (rr >= 6 && rr <= IT + 5);
            const bool vE  = (rr >= 7 && rr <= IT + 6);
            const bool vF  = (rr >= 8);
            float d0 = 0.f, d1 = 0.f, d2 = 0.f, d3 = 0.f;
            if (vA | vC) { d0 = hx[0]; d3 = hx[3]; }
            if (vA | vB | vC | vD | vE | vF) d1 = hx[1];
            if (vK0 | vK1 | vK2 | vA | vC) d2 = hx[2];
            if (vK0) acc[rr]     -= KB0 * d2;
            if (vK1) acc[rr - 1] -= KB1 * d2;
            if (vK2) acc[rr - 2] -= KB2 * d2;
            if (vA)  acc[rr - 3] -= a0 * d0 + m01 * d1 + a1k * d2 + a0 * d3;
            if (vB)  acc[rr - 4] -= m11 * d1;
            if (vC)  acc[rr - 5] -= a1 * d0 + m21k * d1 + a0 * d2 + a1 * d3;
            if (vD)  acc[rr - 6] -= KF1 * d1;
            if (vE)  acc[rr - 7] -= KF2 * d1;
            if (vF)  acc[rr - 8] -= KF3 * d1;
            hx += NH;
        }
    }

    const size_t off = (size_t)i0 * NE + j;
#pragma unroll
    for (int k = 0; k < IT; k++)
        Eob[off + (size_t)k * NE] = Eb[off + (size_t)k * NE] + CFLf * acc[k];
}

// ===========================================================================
// Fused faraday (Hx+Hy): interior slices + boundary strips.
// ===========================================================================
__global__ __launch_bounds__(256)
void faraday_kernel(const float* __restrict__ E,
                    const float* __restrict__ Hx,
                    const float* __restrict__ Hy,
                    const float* __restrict__ pb,
                    const float* __restrict__ pd,
                    const float* __restrict__ pg,
                    float* __restrict__ Hxo,
                    float* __restrict__ Hyo) {
    const int b = blockIdx.z;
    float a0, a1, m01, m11, m21;
    load_M(*pb, *pd, *pg, a0, a1, m01, m11, m21);

    const float* Eb  = E  + (size_t)b * NE * NE;
    const float* Hxb = Hx + (size_t)b * NW * NH;
    const float* Hyb = Hy + (size_t)b * NH * NW;
    float* Hxob = Hxo + (size_t)b * NW * NH;
    float* Hyob = Hyo + (size_t)b * NH * NW;

    if (blockIdx.y >= F_INT_Y) {
        // ---- boundary strips ----
        const int y = blockIdx.y - F_INT_Y;
        if (y < 8) {
            const int i = (y < 2) ? y : 2042 + (y - 2);
            const int j = blockIdx.x * 256 + threadIdx.x;
            if (j >= NH) return;
            faraday_point(i, j, Eb, Hxb, Hyb, a0, a1, m01, m11, m21, Hxob, Hyob);
        } else {
            const int c = y - 8;
            const int j = (c < 2) ? c : 2045 + (c - 2);
            const int i = 2 + blockIdx.x * 256 + threadIdx.x;
            if (i > 2041) return;
            faraday_point(i, j, Eb, Hxb, Hyb, a0, a1, m01, m11, m21, Hxob, Hyob);
        }
        return;
    }

    // ---- interior: i0 = 2 + 8*y, j in [2, 2044] ----
    const int j = 2 + blockIdx.x * 256 + threadIdx.x;
    if (j > 2044) return;
    const int i0 = 2 + blockIdx.y * IT;

    const float m11b = m11 - 1.5f;
    const float m21b = m21 + 2.0f;
    const float a1m2 = a1 - 2.0f;

    float sx[IT], sy[IT];
#pragma unroll
    for (int k = 0; k < IT; k++) { sx[k] = 0.0f; sy[k] = 0.0f; }

    const float* ep = Eb + (size_t)(i0 - 1) * NE + (j - 1);
#pragma unroll
    for (int rr = 0; rr < IT + 4; ++rr) {
        const bool w0 = (rr <= IT - 1);
        const bool w1 = (rr >= 1 && rr <= IT);
        const bool w2 = (rr >= 2 && rr <= IT + 1);
        const bool w3 = (rr >= 3 && rr <= IT + 2);
        const bool w4 = (rr >= 4);
        float e0 = 0.f, e2 = 0.f, e3 = 0.f, e4 = 0.f;
        const float e1 = ep[1];
        if (w1 | w2 | w3) e0 = ep[0];
        if (w0 | w1 | w2 | w3) { e2 = ep[2]; e3 = ep[3]; }
        if (w1) e4 = ep[4];

        const float ty = a0 * e1 + a1 * e3;
        if (w0) { sx[rr] += 0.5f * e2; sy[rr] += ty; }
        if (w1) {
            sx[rr - 1] += a0 * e0 + m01 * e1 + a1m2 * e2 + a0 * e3;
            sy[rr - 1] += m01 * e1 + m11b * e2 + m21b * e3 - 0.5f * e4;
        }
        if (w2) {
            sx[rr - 2] += m11b * e1 + 1.5f * e2;
            sy[rr - 2] += 0.5f * e0 + a1m2 * e1 + 1.5f * e2 + a0 * e3;
        }
        if (w3) {
            sx[rr - 3] += a1 * e0 + m21b * e1 + a0 * e2 + a1 * e3;
            sy[rr - 3] += ty;
        }
        if (w4) sx[rr - 4] -= 0.5f * e1;
        ep += NE;
    }

    const size_t offx = (size_t)i0 * NH + j;
    const size_t offy = (size_t)i0 * NW + j;
#pragma unroll
    for (int k = 0; k < IT; k++) {
        Hxob[offx + (size_t)k * NH] = Hxb[offx + (size_t)k * NH] - CFLf * sx[k];
        Hyob[offy + (size_t)k * NW] = Hyb[offy + (size_t)k * NW] + CFLf * sy[k];
    }
}

// ===========================================================================
extern "C" void kernel_launch(void* const* d_in, const int* in_sizes, int n_in,
                              void* d_out, int out_size) {
    const float* E0  = (const float*)d_in[0];
    const float* Hx0 = (const float*)d_in[1];
    const float* Hy0 = (const float*)d_in[2];
    const float* pb  = (const float*)d_in[3];
    const float* pd  = (const float*)d_in[4];
    const float* pg  = (const float*)d_in[5];

    const int B = in_sizes[0] / (NE * NE);

    const size_t nE  = (size_t)B * NE * NE;
    const size_t nHx = (size_t)B * NW * NH;
    const size_t nHy = (size_t)B * NH * NW;

    float* out = (float*)d_out;
    float* E2  = out;
    float* Hx2 = E2 + nE;
    float* Hy2 = Hx2 + nHx;
    float* E3  = Hy2 + nHy;
    float* Hx3 = E3 + nE;
    float* Hy3 = Hx3 + nHx;
    float* E4  = Hy3 + nHy;
    float* Hx4 = E4 + nE;
    float* Hy4 = Hx4 + nHx;

    dim3 blk(256);
    // amper: x=9 covers boundary rows (2049 cols); interior uses x<8 (j<=2043).
    dim3 gA(9, A_INT_Y + A_BND_Y, B);
    // faraday: x=8 covers both interior (j<=2044) and boundary (2048 cols).
    dim3 gF(8, F_INT_Y + F_BND_Y, B);

    const float* Ein  = E0;
    const float* Hxin = Hx0;
    const float* Hyin = Hy0;
    float* Eouts[3]  = {E2, E3, E4};
    float* Hxouts[3] = {Hx2, Hx3, Hx4};
    float* Hyouts[3] = {Hy2, Hy3, Hy4};

    for (int s = 0; s < 3; s++) {
        amper_kernel<<<gA, blk>>>(Ein, Hxin, Hyin, pb, pd, pg, Eouts[s]);
        faraday_kernel<<<gF, blk>>>(Eouts[s], Hxin, Hyin, pb, pd, pg,
                                    Hxouts[s], Hyouts[s]);
        Ein = Eouts[s]; Hxin = Hxouts[s]; Hyin = Hyouts[s];
    }
}

// round 16
// speedup vs baseline: 1.2486x; 1.0494x over previous
#include <cuda_runtime.h>

#define NE 2049   // E is NE x NE
#define NH 2048   // Hx cols / Hy rows
#define NW 2047   // Hx rows / Hy cols
#define CFLf 0.35f

#define KF0 (-11.0f/6.0f)
#define KF1 (3.0f)
#define KF2 (-1.5f)
#define KF3 (1.0f/3.0f)
#define KB0 (-1.0f/3.0f)
#define KB1 (1.5f)
#define KB2 (-3.0f)
#define KB3 (11.0f/6.0f)

#define IT 8
#define A_INT_Y 254   // amper interior: i0 = 5 + 8*y, i in [5,2036]
#define A_BND_Y 27    // 17 row strips + 10 col strips
#define F_INT_Y 255   // faraday interior: i0 = 2 + 8*y, i in [2,2041]
#define F_BND_Y 13    // 8 row strips + 5 col strips

__device__ __forceinline__ void load_M(float beta, float delta, float gamma,
                                       float& a0, float& a1,
                                       float& m01, float& m11, float& m21) {
    a0  = -0.25f * beta + 0.1f * gamma;
    a1  =  0.25f * beta - 0.1f * gamma;
    m01 =  0.25f * beta + delta - 0.5f - 0.1f * gamma;
    m11 = -2.0f * delta;
    m21 = -0.25f * beta + delta + 0.5f + 0.1f * gamma;
}

// ===========================================================================
// Scalar point functions (verified) — boundary strips.
// ===========================================================================
__device__ void amper_point(int i, int j,
                            const float* __restrict__ Eb,
                            const float* __restrict__ Hxb,
                            const float* __restrict__ Hyb,
                            float a0, float a1, float m01, float m11, float m21,
                            float* __restrict__ Eob) {
    const bool ic = (i >= 2 && i <= NE - 3);
    const bool jc = (j >= 2 && j <= NE - 3);
    float s1 = 0.0f, s2 = 0.0f;

    if (ic && jc) {
        const float* r0 = Hyb + (size_t)(i - 2) * NW + (j - 2);
        const float* r1 = r0 + NW;
        const float* r2 = r1 + NW;
        const float* r3 = r2 + NW;
        s1 += a0  * r0[0] + a1  * r0[2]
            + m01 * r1[0] + m11 * r1[1] + m21 * r1[2]
            + a1  * r2[0] + a0  * r2[2]
            + a0  * r3[0] + a1  * r3[2];
        const float* x0 = Hxb + (size_t)(i - 2) * NH + (j - 2);
        const float* x1 = x0 + NH;
        const float* x2 = x1 + NH;
        s2 += a0 * x0[0] + m01 * x0[1] + a1 * x0[2] + a0 * x0[3]
            + m11 * x1[1]
            + a1 * x2[0] + m21 * x2[1] + a0 * x2[2] + a1 * x2[3];
    }
    if (i >= 1 && j <= NE - 6) {
        const float* r = Hyb + (size_t)(i - 1) * NW + j;
        s1 += KF0 * r[0] + KF1 * r[1] + KF2 * r[2] + KF3 * r[3];
    }
    if (i <= NE - 2 && j >= 5) {
        const float* r = Hyb + (size_t)i * NW + (j - 5);
        s1 += KB0 * r[0] + KB1 * r[1] + KB2 * r[2] + KB3 * r[3];
    }
    if (ic && (j == 1 || j == 2)) {
        const float* r = Hyb + (size_t)(i - 1) * NW + (j - 1);
        s1 += -r[0] + 3.0f * r[1] - 3.0f * r[2] + r[3];
    }
    if (ic && (j == NE - 3 || j == NE - 2)) {
        const float* r = Hyb + (size_t)i * NW + (j - 4);
        s1 += r[0] - 3.0f * r[1] + 3.0f * r[2] - r[3];
    }
    if (i <= NE - 6 && j >= 1) {
        const float* x = Hxb + (size_t)i * NH + (j - 1);
        s2 += KF0 * x[0] + KF1 * x[NH] + KF2 * x[2 * NH] + KF3 * x[3 * NH];
    }
    if (i >= 5 && j <= NE - 2) {
        const float* x = Hxb + (size_t)(i - 5) * NH + j;
        s2 += KB0 * x[0] + KB1 * x[NH] + KB2 * x[2 * NH] + KB3 * x[3 * NH];
    }
    if ((i == 1 || i == 2) && jc) {
        const float* x = Hxb + (size_t)(i - 1) * NH + (j - 1);
        s2 += -x[0] + 3.0f * x[NH] - 3.0f * x[2 * NH] + x[3 * NH];
    }
    if ((i == NE - 3 || i == NE - 2) && jc) {
        const float* x = Hxb + (size_t)(i - 4) * NH + j;
        s2 += x[0] - 3.0f * x[NH] + 3.0f * x[2 * NH] - x[3 * NH];
    }
    Eob[(size_t)i * NE + j] = Eb[(size_t)i * NE + j] + CFLf * (s1 - s2);
}

__device__ void faraday_point(int i, int j,
                              const float* __restrict__ Eb,
                              const float* __restrict__ Hxb,
                              const float* __restrict__ Hyb,
                              float a0, float a1, float m01, float m11, float m21,
                              float* __restrict__ Hxob,
                              float* __restrict__ Hyob) {
    if (i < NW && j < NH) {
        float s3 = 0.0f;
        if (j >= 1 && j <= NH - 2) {
            const float* e0 = Eb + (size_t)i * NE + (j - 1);
            const float* e1 = e0 + NE;
            const float* e2 = e1 + NE;
            s3 += a0 * e0[0] + m01 * e0[1] + a1 * e0[2] + a0 * e0[3]
                + m11 * e1[1]
                + a1 * e2[0] + m21 * e2[1] + a0 * e2[2] + a1 * e2[3];
        }
        if (i <= NH - 4) {
            const float* e = Eb + (size_t)(i + 1) * NE + j;
            s3 += -1.5f * e[0] + 2.0f * e[NE] - 0.5f * e[2 * NE];
        }
        if (i >= 2) {
            const float* e = Eb + (size_t)(i - 1) * NE + (j + 1);
            s3 += 0.5f * e[0] - 2.0f * e[NE] + 1.5f * e[2 * NE];
        }
        const size_t off = (size_t)i * NH + j;
        Hxob[off] = Hxb[off] - CFLf * s3;
    }
    if (i < NH && j < NW) {
        float s4 = 0.0f;
        if (i >= 1 && i <= NH - 2) {
            const float* e0 = Eb + (size_t)(i - 1) * NE + j;
            const float* e1 = e0 + NE;
            const float* e2 = e1 + NE;
            const float* e3 = e2 + NE;
            s4 += a0  * e0[0] + a1  * e0[2]
                + m01 * e1[0] + m11 * e1[1] + m21 * e1[2]
                + a1  * e2[0] + a0  * e2[2]
                + a0  * e3[0] + a1  * e3[2];
        }
        if (j <= NH - 4) {
            const float* e = Eb + (size_t)i * NE + (j + 1);
            s4 += -1.5f * e[0] + 2.0f * e[1] - 0.5f * e[2];
        }
        if (j >= 2) {
            const float* e = Eb + (size_t)(i + 1) * NE + (j - 1);
            s4 += 0.5f * e[0] - 2.0f * e[1] + 1.5f * e[2];
        }
        const size_t off = (size_t)i * NW + j;
        Hyob[off] = Hyb[off] + CFLf * s4;
    }
}

// ===========================================================================
// Fused amper: interior (IT=8, JT=2 adjacent columns/thread) + boundary.
// Thread q owns columns j0 = 5+2q and j0+1 (share a 10-wide row window).
// ===========================================================================
__global__ __launch_bounds__(256)
void amper_kernel(const float* __restrict__ E,
                  const float* __restrict__ Hx,
                  const float* __restrict__ Hy,
                  const float* __restrict__ pb,
                  const float* __restrict__ pd,
                  const float* __restrict__ pg,
                  float* __restrict__ Eo) {
    const int b = blockIdx.z;
    float a0, a1, m01, m11, m21;
    load_M(*pb, *pd, *pg, a0, a1, m01, m11, m21);

    const float* Eb  = E  + (size_t)b * NE * NE;
    const float* Hxb = Hx + (size_t)b * NW * NH;
    const float* Hyb = Hy + (size_t)b * NH * NW;
    float* Eob = Eo + (size_t)b * NE * NE;

    if (blockIdx.y >= A_INT_Y) {
        // ---- boundary strips ----
        const int y = blockIdx.y - A_INT_Y;
        if (y < 17) {
            const int i = (y < 5) ? y : 2037 + (y - 5);
            const int j = blockIdx.x * 256 + threadIdx.x;
            if (j >= NE) return;
            amper_point(i, j, Eb, Hxb, Hyb, a0, a1, m01, m11, m21, Eob);
        } else {
            const int c = y - 17;
            const int j = (c < 5) ? c : 2044 + (c - 5);
            const int i = 5 + blockIdx.x * 256 + threadIdx.x;
            if (i > 2036) return;
            amper_point(i, j, Eb, Hxb, Hyb, a0, a1, m01, m11, m21, Eob);
        }
        return;
    }

    // ---- interior: pairs j0 = 5 + 2q, q in [0,1019]; i0 = 5 + 8*y ----
    const int q = blockIdx.x * 256 + threadIdx.x;
    if (q > 1019) return;
    const int j0 = 5 + 2 * q;              // j0 in [5, 2043]
    const bool valid1 = (j0 + 1 <= 2043);  // false only for j0 == 2043
    const int i0 = 5 + blockIdx.y * IT;

    const float a1k  = a1 + KB3;
    const float m21k = m21 + KF0;

    float ac0[IT], ac1[IT];
#pragma unroll
    for (int k = 0; k < IT; k++) { ac0[k] = 0.0f; ac1[k] = 0.0f; }

    // ---- s1: Hy rows i0-2 .. i0+8, shared window cols j0-5 .. j0+4 ----
    {
        const float* hy = Hyb + (size_t)(i0 - 2) * NW + (j0 - 5);
#pragma unroll
        for (int rr = 0; rr < IT + 3; ++rr) {
            const bool uA = (rr <= IT - 1);
            const bool uB = (rr >= 1 && rr <= IT);
            const bool uC = (rr >= 2 && rr <= IT + 1);
            const bool uD = (rr >= 3);
            float v0 = 0.f, v1 = 0.f, v2 = 0.f, v7 = 0.f, v8 = 0.f, v9 = 0.f;
            const float v3 = hy[3];
            const float v4 = hy[4];
            const float v5 = hy[5];
            const float v6 = hy[6];
            if (uC) { v0 = hy[0]; v1 = hy[1]; v2 = hy[2]; }
            if (uB) {
                v7 = hy[7]; v8 = hy[8];
                if (valid1) v9 = hy[9];    // col1 KF3; in-bounds only when valid1
            }
            const float t0 = a0 * v3 + a1 * v5;
            const float t1 = a0 * v4 + a1 * v6;
            if (uA) { ac0[rr] += t0; ac1[rr] += t1; }
            if (uB) {
                ac0[rr - 1] += m01 * v3 + m11 * v4 + m21k * v5
                             + KF1 * v6 + KF2 * v7 + KF3 * v8;
                ac1[rr - 1] += m01 * v4 + m11 * v5 + m21k * v6
                             + KF1 * v7 + KF2 * v8 + KF3 * v9;
            }
            if (uC) {
                ac0[rr - 2] += KB0 * v0 + KB1 * v1 + KB2 * v2
                             + a1k * v3 + a0 * v5;
                ac1[rr - 2] += KB0 * v1 + KB1 * v2 + KB2 * v3
                             + a1k * v4 + a0 * v6;
            }
            if (uD) { ac0[rr - 3] += t0; ac1[rr - 3] += t1; }
            hy += NW;
        }
    }

    // ---- s2 (subtract): Hx rows i0-5 .. i0+10, shared window j0-2 .. j0+2 ----
    {
        const float* hx = Hxb + (size_t)(i0 - 5) * NH + (j0 - 2);
#pragma unroll
        for (int rr = 0; rr < IT + 8; ++rr) {
            const bool vK0 = (rr <= IT - 1);
            const bool vK1 = (rr >= 1 && rr <= IT);
            const bool vK2 = (rr >= 2 && rr <= IT + 1);
            const bool vA  = (rr >= 3 && rr <= IT + 2);
            const bool vB  = (rr >= 4 && rr <= IT + 3);
            const bool vC  = (rr >= 5 && rr <= IT + 4);
            const bool vD  = (rr >= 6 && rr <= IT + 5);
            const bool vE  = (rr >= 7 && rr <= IT + 6);
            const bool vF  = (rr >= 8);
            // w1 (j0-1) and w2 (j0) feed col0/col1 KF terms through rr=IT+7:
            // load unconditionally (all rows/cols in-bounds).
            const float w1 = hx[1];
            const float w2 = hx[2];
            float w0 = 0.f, w3 = 0.f, w4 = 0.f;
            if (vA | vC) { w0 = hx[0]; w4 = hx[4]; }
            if (vK0 | vK1 | vK2 | vA | vC) { w3 = hx[3]; }
            if (vK0) { ac0[rr]     -= KB0 * w2; ac1[rr]     -= KB0 * w3; }
            if (vK1) { ac0[rr - 1] -= KB1 * w2; ac1[rr - 1] -= KB1 * w3; }
            if (vK2) { ac0[rr - 2] -= KB2 * w2; ac1[rr - 2] -= KB2 * w3; }
            if (vA) {
                ac0[rr - 3] -= a0 * w0 + m01 * w1 + a1k * w2 + a0 * w3;
                ac1[rr - 3] -= a0 * w1 + m01 * w2 + a1k * w3 + a0 * w4;
            }
            if (vB) { ac0[rr - 4] -= m11 * w1; ac1[rr - 4] -= m11 * w2; }
            if (vC) {
                ac0[rr - 5] -= a1 * w0 + m21k * w1 + a0 * w2 + a1 * w3;
                ac1[rr - 5] -= a1 * w1 + m21k * w2 + a0 * w3 + a1 * w4;
            }
            if (vD) { ac0[rr - 6] -= KF1 * w1; ac1[rr - 6] -= KF1 * w2; }
            if (vE) { ac0[rr - 7] -= KF2 * w1; ac1[rr - 7] -= KF2 * w2; }
            if (vF) { ac0[rr - 8] -= KF3 * w1; ac1[rr - 8] -= KF3 * w2; }
            hx += NH;
        }
    }

    const size_t off = (size_t)i0 * NE + j0;
#pragma unroll
    for (int k = 0; k < IT; k++) {
        const size_t o = off + (size_t)k * NE;
        Eob[o] = Eb[o] + CFLf * ac0[k];
        if (valid1) Eob[o + 1] = Eb[o + 1] + CFLf * ac1[k];
    }
}

// ===========================================================================
// Fused faraday (Hx+Hy): interior slices + boundary strips. (R5, unchanged.)
// ===========================================================================
__global__ __launch_bounds__(256)
void faraday_kernel(const float* __restrict__ E,
                    const float* __restrict__ Hx,
                    const float* __restrict__ Hy,
                    const float* __restrict__ pb,
                    const float* __restrict__ pd,
                    const float* __restrict__ pg,
                    float* __restrict__ Hxo,
                    float* __restrict__ Hyo) {
    const int b = blockIdx.z;
    float a0, a1, m01, m11, m21;
    load_M(*pb, *pd, *pg, a0, a1, m01, m11, m21);

    const float* Eb  = E  + (size_t)b * NE * NE;
    const float* Hxb = Hx + (size_t)b * NW * NH;
    const float* Hyb = Hy + (size_t)b * NH * NW;
    float* Hxob = Hxo + (size_t)b * NW * NH;
    float* Hyob = Hyo + (size_t)b * NH * NW;

    if (blockIdx.y >= F_INT_Y) {
        // ---- boundary strips ----
        const int y = blockIdx.y - F_INT_Y;
        if (y < 8) {
            const int i = (y < 2) ? y : 2042 + (y - 2);
            const int j = blockIdx.x * 256 + threadIdx.x;
            if (j >= NH) return;
            faraday_point(i, j, Eb, Hxb, Hyb, a0, a1, m01, m11, m21, Hxob, Hyob);
        } else {
            const int c = y - 8;
            const int j = (c < 2) ? c : 2045 + (c - 2);
            const int i = 2 + blockIdx.x * 256 + threadIdx.x;
            if (i > 2041) return;
            faraday_point(i, j, Eb, Hxb, Hyb, a0, a1, m01, m11, m21, Hxob, Hyob);
        }
        return;
    }

    // ---- interior: i0 = 2 + 8*y, j in [2, 2044] ----
    const int j = 2 + blockIdx.x * 256 + threadIdx.x;
    if (j > 2044) return;
    const int i0 = 2 + blockIdx.y * IT;

    const float m11b = m11 - 1.5f;
    const float m21b = m21 + 2.0f;
    const float a1m2 = a1 - 2.0f;

    float sx[IT], sy[IT];
#pragma unroll
    for (int k = 0; k < IT; k++) { sx[k] = 0.0f; sy[k] = 0.0f; }

    const float* ep = Eb + (size_t)(i0 - 1) * NE + (j - 1);
#pragma unroll
    for (int rr = 0; rr < IT + 4; ++rr) {
        const bool w0 = (rr <= IT - 1);
        const bool w1 = (rr >= 1 && rr <= IT);
        const bool w2 = (rr >= 2 && rr <= IT + 1);
        const bool w3 = (rr >= 3 && rr <= IT + 2);
        const bool w4 = (rr >= 4);
        float e0 = 0.f, e2 = 0.f, e3 = 0.f, e4 = 0.f;
        const float e1 = ep[1];
        if (w1 | w2 | w3) e0 = ep[0];
        if (w0 | w1 | w2 | w3) { e2 = ep[2]; e3 = ep[3]; }
        if (w1) e4 = ep[4];

        const float ty = a0 * e1 + a1 * e3;
        if (w0) { sx[rr] += 0.5f * e2; sy[rr] += ty; }
        if (w1) {
            sx[rr - 1] += a0 * e0 + m01 * e1 + a1m2 * e2 + a0 * e3;
            sy[rr - 1] += m01 * e1 + m11b * e2 + m21b * e3 - 0.5f * e4;
        }
        if (w2) {
            sx[rr - 2] += m11b * e1 + 1.5f * e2;
            sy[rr - 2] += 0.5f * e0 + a1m2 * e1 + 1.5f * e2 + a0 * e3;
        }
        if (w3) {
            sx[rr - 3] += a1 * e0 + m21b * e1 + a0 * e2 + a1 * e3;
            sy[rr - 3] += ty;
        }
        if (w4) sx[rr - 4] -= 0.5f * e1;
        ep += NE;
    }

    const size_t offx = (size_t)i0 * NH + j;
    const size_t offy = (size_t)i0 * NW + j;
#pragma unroll
    for (int k = 0; k < IT; k++) {
        Hxob[offx + (size_t)k * NH] = Hxb[offx + (size_t)k * NH] - CFLf * sx[k];
        Hyob[offy + (size_t)k * NW] = Hyb[offy + (size_t)k * NW] + CFLf * sy[k];
    }
}

// ===========================================================================
extern "C" void kernel_launch(void* const* d_in, const int* in_sizes, int n_in,
                              void* d_out, int out_size) {
    const float* E0  = (const float*)d_in[0];
    const float* Hx0 = (const float*)d_in[1];
    const float* Hy0 = (const float*)d_in[2];
    const float* pb  = (const float*)d_in[3];
    const float* pd  = (const float*)d_in[4];
    const float* pg  = (const float*)d_in[5];

    const int B = in_sizes[0] / (NE * NE);

    const size_t nE  = (size_t)B * NE * NE;
    const size_t nHx = (size_t)B * NW * NH;
    const size_t nHy = (size_t)B * NH * NW;

    float* out = (float*)d_out;
    float* E2  = out;
    float* Hx2 = E2 + nE;
    float* Hy2 = Hx2 + nHx;
    float* E3  = Hy2 + nHy;
    float* Hx3 = E3 + nE;
    float* Hy3 = Hx3 + nHx;
    float* E4  = Hy3 + nHy;
    float* Hx4 = E4 + nE;
    float* Hy4 = Hx4 + nHx;

    dim3 blk(256);
    // amper: x=9 covers boundary rows (2049 cols); interior uses q<=1019 (x<4).
    dim3 gA(9, A_INT_Y + A_BND_Y, B);
    // faraday: x=8 covers both interior (j<=2044) and boundary (2048 cols).
    dim3 gF(8, F_INT_Y + F_BND_Y, B);

    const float* Ein  = E0;
    const float* Hxin = Hx0;
    const float* Hyin = Hy0;
    float* Eouts[3]  = {E2, E3, E4};
    float* Hxouts[3] = {Hx2, Hx3, Hx4};
    float* Hyouts[3] = {Hy2, Hy3, Hy4};

    for (int s = 0; s < 3; s++) {
        amper_kernel<<<gA, blk>>>(Ein, Hxin, Hyin, pb, pd, pg, Eouts[s]);
        faraday_kernel<<<gF, blk>>>(Eouts[s], Hxin, Hyin, pb, pd, pg,
                                    Hxouts[s], Hyouts[s]);
        Ein = Eouts[s]; Hxin = Hxouts[s]; Hyin = Hyouts[s];
    }
}